// round 3
// baseline (speedup 1.0000x reference)
#include <cuda_runtime.h>

#define SEQ    2048
#define DMODEL 2048
#define NHEAD  16
#define HDIM   128
#define BATCH  2

// ---------------- scratch (no allocations allowed) ----------------
__device__ float g_q[BATCH * SEQ * DMODEL];    // 64 MB
__device__ float g_k[BATCH * SEQ * HDIM];      // 4 MB
__device__ float g_v[BATCH * SEQ * HDIM];      // 4 MB
__device__ float g_attn[BATCH * SEQ * DMODEL]; // 64 MB

// ---------------- GEMM: C[M,N] = A[M,K] @ W[N,K]^T (both K-major) --------
// 128x128 tile, BK=16, 256 threads, 8x8 register frags.
// Requires M%128==0, N%128==0, K%16==0 (all shapes here satisfy this).
__global__ __launch_bounds__(256) void sgemm_nt(const float* __restrict__ A,
                                                const float* __restrict__ W,
                                                float* __restrict__ C,
                                                int M, int N, int K) {
    __shared__ float As[16][132];
    __shared__ float Bs[16][132];
    const int t  = threadIdx.x;
    const int m0 = blockIdx.y * 128;
    const int n0 = blockIdx.x * 128;
    const int tx = t & 15, ty = t >> 4;
    const int r  = t >> 2;             // 0..63
    const int kq = (t & 3) * 4;        // 0,4,8,12

    float acc[8][8] = {};

    for (int k0 = 0; k0 < K; k0 += 16) {
        float4 a0 = *(const float4*)(A + (size_t)(m0 + r)      * K + k0 + kq);
        float4 a1 = *(const float4*)(A + (size_t)(m0 + r + 64) * K + k0 + kq);
        float4 b0 = *(const float4*)(W + (size_t)(n0 + r)      * K + k0 + kq);
        float4 b1 = *(const float4*)(W + (size_t)(n0 + r + 64) * K + k0 + kq);
        __syncthreads();   // guard previous iteration's smem reads
        As[kq+0][r]    = a0.x; As[kq+1][r]    = a0.y; As[kq+2][r]    = a0.z; As[kq+3][r]    = a0.w;
        As[kq+0][r+64] = a1.x; As[kq+1][r+64] = a1.y; As[kq+2][r+64] = a1.z; As[kq+3][r+64] = a1.w;
        Bs[kq+0][r]    = b0.x; Bs[kq+1][r]    = b0.y; Bs[kq+2][r]    = b0.z; Bs[kq+3][r]    = b0.w;
        Bs[kq+0][r+64] = b1.x; Bs[kq+1][r+64] = b1.y; Bs[kq+2][r+64] = b1.z; Bs[kq+3][r+64] = b1.w;
        __syncthreads();
        #pragma unroll
        for (int k = 0; k < 16; k++) {
            float a[8], b[8];
            *(float4*)(a)     = *(const float4*)&As[k][ty*8];
            *(float4*)(a + 4) = *(const float4*)&As[k][ty*8 + 4];
            *(float4*)(b)     = *(const float4*)&Bs[k][tx*8];
            *(float4*)(b + 4) = *(const float4*)&Bs[k][tx*8 + 4];
            #pragma unroll
            for (int i = 0; i < 8; i++)
                #pragma unroll
                for (int j = 0; j < 8; j++)
                    acc[i][j] += a[i] * b[j];
        }
    }
    #pragma unroll
    for (int i = 0; i < 8; i++) {
        float* cp = C + (size_t)(m0 + ty*8 + i) * N + n0 + tx*8;
        *(float4*)(cp)     = make_float4(acc[i][0], acc[i][1], acc[i][2], acc[i][3]);
        *(float4*)(cp + 4) = make_float4(acc[i][4], acc[i][5], acc[i][6], acc[i][7]);
    }
}

// ---------------- RoPE (torch view_as_complex pair layout) ----------------
// q: [B*SEQ, rowLen], pair p in a row -> cols (2p, 2p+1); within-head pair idx = p % 64.
__global__ void rope_kernel(float* __restrict__ q,
                            const float* __restrict__ cosT,
                            const float* __restrict__ sinT,
                            int rowLen, int nPairs) {
    int idx = blockIdx.x * blockDim.x + threadIdx.x;
    if (idx >= nPairs) return;
    int pairsPerRow = rowLen >> 1;
    int row = idx / pairsPerRow;
    int pr  = idx - row * pairsPerRow;
    int s   = row & (SEQ - 1);   // row % SEQ (rows = B*SEQ, SEQ pow2)
    int p   = pr & 63;           // HD/2 = 64
    float c  = cosT[s * 64 + p];
    float sn = sinT[s * 64 + p];
    float2 v = *(float2*)(q + (size_t)row * rowLen + pr * 2);
    float x0 = v.x, x1 = v.y;
    *(float2*)(q + (size_t)row * rowLen + pr * 2) =
        make_float2(x0 * c - x1 * sn, x0 * sn + x1 * c);
}

// ---------------- Flash attention (causal, MQA) ----------------
// Grid (SEQ/64, NHEAD, BATCH), 256 threads. Q/K/V tiles 64x128 in smem,
// 4x4 score frags per thread (16x16 thread grid), O frag 4 rows x 8 cols.
// Output written as [B, S, H, HD] (== [B,S,D] for the O-projection).
__global__ __launch_bounds__(256) void attn_kernel(const float* __restrict__ gq,
                                                   const float* __restrict__ gk,
                                                   const float* __restrict__ gv,
                                                   float* __restrict__ gout) {
    extern __shared__ float smem[];
    float* sQ = smem;              // 64*132
    float* sK = sQ + 64 * 132;     // 64*132
    float* sV = sK + 64 * 132;     // 64*132
    float* sP = sV + 64 * 132;     // 64*68

    const int b  = blockIdx.z, h = blockIdx.y;
    const int q0 = blockIdx.x * 64;
    const int t  = threadIdx.x, tx = t & 15, ty = t >> 4;
    const float scale = 0.08838834764831845f; // 1/sqrt(128)

    // load Q tile (rows q0..q0+63, head h's 128 columns)
    const float* qbase = gq + ((size_t)b * SEQ + q0) * DMODEL + h * HDIM;
    for (int f = t; f < 2048; f += 256) {
        int r = f >> 5, c4 = (f & 31) << 2;
        *(float4*)&sQ[r * 132 + c4] = *(const float4*)(qbase + (size_t)r * DMODEL + c4);
    }

    float o[4][8];
    float m_i[4], l_i[4];
    #pragma unroll
    for (int i = 0; i < 4; i++) {
        m_i[i] = -1e30f; l_i[i] = 0.f;
        #pragma unroll
        for (int c = 0; c < 8; c++) o[i][c] = 0.f;
    }

    for (int kv0 = 0; kv0 <= q0; kv0 += 64) {
        __syncthreads();  // previous tile's sK/sV/sP reads done
        const float* kb = gk + ((size_t)b * SEQ + kv0) * HDIM;
        const float* vb = gv + ((size_t)b * SEQ + kv0) * HDIM;
        for (int f = t; f < 2048; f += 256) {
            int r = f >> 5, c4 = (f & 31) << 2;
            *(float4*)&sK[r * 132 + c4] = *(const float4*)(kb + (size_t)r * HDIM + c4);
            *(float4*)&sV[r * 132 + c4] = *(const float4*)(vb + (size_t)r * HDIM + c4);
        }
        __syncthreads();

        // S = Q K^T (4x4 frag per thread)
        float sf[4][4] = {};
        #pragma unroll
        for (int d = 0; d < 128; d += 4) {
            float4 a[4], bb[4];
            #pragma unroll
            for (int i = 0; i < 4; i++) a[i]  = *(const float4*)&sQ[(ty*4 + i) * 132 + d];
            #pragma unroll
            for (int j = 0; j < 4; j++) bb[j] = *(const float4*)&sK[(tx*4 + j) * 132 + d];
            #pragma unroll
            for (int i = 0; i < 4; i++)
                #pragma unroll
                for (int j = 0; j < 4; j++)
                    sf[i][j] += a[i].x * bb[j].x + a[i].y * bb[j].y
                              + a[i].z * bb[j].z + a[i].w * bb[j].w;
        }

        const bool diag = (kv0 == q0);
        #pragma unroll
        for (int i = 0; i < 4; i++)
            #pragma unroll
            for (int j = 0; j < 4; j++) {
                float v = sf[i][j] * scale;
                if (diag && (tx*4 + j) > (ty*4 + i)) v = -1e30f;
                sf[i][j] = v;
            }

        // online softmax per owned row (16-lane subgroup reduce over tx)
        #pragma unroll
        for (int i = 0; i < 4; i++) {
            float mt = fmaxf(fmaxf(sf[i][0], sf[i][1]), fmaxf(sf[i][2], sf[i][3]));
            #pragma unroll
            for (int off = 8; off >= 1; off >>= 1)
                mt = fmaxf(mt, __shfl_xor_sync(0xffffffffu, mt, off));
            float mn   = fmaxf(m_i[i], mt);
            float corr = __expf(m_i[i] - mn);
            m_i[i] = mn;
            float sum = 0.f;
            #pragma unroll
            for (int j = 0; j < 4; j++) {
                float p = __expf(sf[i][j] - mn);
                sf[i][j] = p;
                sum += p;
            }
            #pragma unroll
            for (int off = 8; off >= 1; off >>= 1)
                sum += __shfl_xor_sync(0xffffffffu, sum, off);
            l_i[i] = l_i[i] * corr + sum;
            #pragma unroll
            for (int c = 0; c < 8; c++) o[i][c] *= corr;
            *(float4*)&sP[(ty*4 + i) * 68 + tx*4] =
                make_float4(sf[i][0], sf[i][1], sf[i][2], sf[i][3]);
        }
        __syncthreads();

        // O += P @ V  (thread owns rows ty*4..+4, cols tx*8..+8)
        #pragma unroll 4
        for (int j = 0; j < 64; j += 4) {
            float pr[4][4];
            #pragma unroll
            for (int i = 0; i < 4; i++) {
                float4 pv = *(const float4*)&sP[(ty*4 + i) * 68 + j];
                pr[i][0] = pv.x; pr[i][1] = pv.y; pr[i][2] = pv.z; pr[i][3] = pv.w;
            }
            #pragma unroll
            for (int jj = 0; jj < 4; jj++) {
                float4 v0 = *(const float4*)&sV[(j + jj) * 132 + tx*8];
                float4 v1 = *(const float4*)&sV[(j + jj) * 132 + tx*8 + 4];
                #pragma unroll
                for (int i = 0; i < 4; i++) {
                    float p = pr[i][jj];
                    o[i][0] += p * v0.x; o[i][1] += p * v0.y;
                    o[i][2] += p * v0.z; o[i][3] += p * v0.w;
                    o[i][4] += p * v1.x; o[i][5] += p * v1.y;
                    o[i][6] += p * v1.z; o[i][7] += p * v1.w;
                }
            }
        }
    }

    // epilogue: normalize, write [B,S,H,HD]
    #pragma unroll
    for (int i = 0; i < 4; i++) {
        float inv = 1.f / l_i[i];
        size_t off = (((size_t)b * SEQ + q0 + ty*4 + i) * NHEAD + h) * HDIM + tx*8;
        *(float4*)(gout + off)     = make_float4(o[i][0]*inv, o[i][1]*inv, o[i][2]*inv, o[i][3]*inv);
        *(float4*)(gout + off + 4) = make_float4(o[i][4]*inv, o[i][5]*inv, o[i][6]*inv, o[i][7]*inv);
    }
}

// ---------------- launch ----------------
extern "C" void kernel_launch(void* const* d_in, const int* in_sizes, int n_in,
                              void* d_out, int out_size) {
    const float* x  = (const float*)d_in[0];
    const float* Wq = (const float*)d_in[1];
    const float* Wk = (const float*)d_in[2];
    const float* Wv = (const float*)d_in[3];
    const float* Wo = (const float*)d_in[4];
    const float* rc = (const float*)d_in[5];
    const float* rs = (const float*)d_in[6];
    float* out = (float*)d_out;

    float *q, *k, *v, *attn;
    cudaGetSymbolAddress((void**)&q,    g_q);
    cudaGetSymbolAddress((void**)&k,    g_k);
    cudaGetSymbolAddress((void**)&v,    g_v);
    cudaGetSymbolAddress((void**)&attn, g_attn);

    const int M = BATCH * SEQ;  // 4096

    // projections
    sgemm_nt<<<dim3(DMODEL / 128, M / 128), 256>>>(x, Wq, q, M, DMODEL, DMODEL);
    sgemm_nt<<<dim3(1,            M / 128), 256>>>(x, Wk, k, M, HDIM,   DMODEL);
    sgemm_nt<<<dim3(1,            M / 128), 256>>>(x, Wv, v, M, HDIM,   DMODEL);

    // RoPE on Q (per head) and K (single head)
    int nPairsQ = M * (DMODEL / 2);
    rope_kernel<<<(nPairsQ + 255) / 256, 256>>>(q, rc, rs, DMODEL, nPairsQ);
    int nPairsK = M * (HDIM / 2);
    rope_kernel<<<(nPairsK + 255) / 256, 256>>>(k, rc, rs, HDIM, nPairsK);

    // flash attention (116 KB dynamic smem; idempotent attribute set, capture-safe)
    const int smemBytes = (3 * 64 * 132 + 64 * 68) * (int)sizeof(float);  // 118784
    cudaFuncSetAttribute(attn_kernel, cudaFuncAttributeMaxDynamicSharedMemorySize, smemBytes);
    attn_kernel<<<dim3(SEQ / 64, NHEAD, BATCH), 256, smemBytes>>>(q, k, v, attn);

    // output projection
    sgemm_nt<<<dim3(DMODEL / 128, M / 128), 256>>>(attn, Wo, out, M, DMODEL, DMODEL);
}

// round 6
// speedup vs baseline: 1.4030x; 1.4030x over previous
#include <cuda_runtime.h>
#include <cuda_bf16.h>
#include <cstdint>

#define SEQ    2048
#define DMODEL 2048
#define NHEAD  16
#define HDIM   128
#define BATCH  2
#define MROWS  (BATCH * SEQ)   // 4096

// single dynamic-smem symbol shared by all kernels (CUDA requires consistent type)
extern __shared__ char dyn_smem[];

// ---------------- scratch (no allocations allowed) ----------------
__device__ float g_q[MROWS * DMODEL];
__device__ float g_k[MROWS * HDIM];
__device__ float g_v[MROWS * HDIM];
__device__ float g_attn[MROWS * DMODEL];

__device__ __nv_bfloat16 g_xh[MROWS * DMODEL],  g_xl[MROWS * DMODEL];
__device__ __nv_bfloat16 g_ah[MROWS * DMODEL],  g_al[MROWS * DMODEL];
__device__ __nv_bfloat16 g_wqh[DMODEL * DMODEL], g_wql[DMODEL * DMODEL];
__device__ __nv_bfloat16 g_woh[DMODEL * DMODEL], g_wol[DMODEL * DMODEL];
__device__ __nv_bfloat16 g_wkh[HDIM * DMODEL],   g_wkl[HDIM * DMODEL];
__device__ __nv_bfloat16 g_wvh[HDIM * DMODEL],   g_wvl[HDIM * DMODEL];

// ---------------- helpers (base sm_100 legal: ldmatrix / mma.sync / cp.async) ----------------
__device__ __forceinline__ uint32_t smem_to_u32(const void* p) {
    uint32_t a;
    asm("{ .reg .u64 t; cvta.to.shared.u64 t, %1; cvt.u32.u64 %0, t; }" : "=r"(a) : "l"(p));
    return a;
}

#define CP_ASYNC16(saddr, gptr) \
    asm volatile("cp.async.cg.shared.global [%0], [%1], 16;" :: "r"(saddr), "l"(gptr))
#define CP_COMMIT() asm volatile("cp.async.commit_group;" ::: "memory")
#define CP_WAIT(n)  asm volatile("cp.async.wait_group %0;" :: "n"(n) : "memory")

__device__ __forceinline__ void ldsm_x4(uint32_t& r0, uint32_t& r1, uint32_t& r2, uint32_t& r3,
                                        uint32_t addr) {
    asm volatile("ldmatrix.sync.aligned.m8n8.x4.shared.b16 {%0,%1,%2,%3}, [%4];"
                 : "=r"(r0), "=r"(r1), "=r"(r2), "=r"(r3) : "r"(addr));
}

__device__ __forceinline__ void mma16816(float* d, const uint32_t* a, uint32_t b0, uint32_t b1) {
    asm volatile(
        "mma.sync.aligned.m16n8k16.row.col.f32.bf16.bf16.f32 "
        "{%0,%1,%2,%3}, {%4,%5,%6,%7}, {%8,%9}, {%0,%1,%2,%3};"
        : "+f"(d[0]), "+f"(d[1]), "+f"(d[2]), "+f"(d[3])
        : "r"(a[0]), "r"(a[1]), "r"(a[2]), "r"(a[3]), "r"(b0), "r"(b1));
}

// ---------------- fp32 -> bf16 hi/lo split ----------------
__global__ void split_bf16(const float* __restrict__ src,
                           __nv_bfloat16* __restrict__ hi,
                           __nv_bfloat16* __restrict__ lo, int n) {
    int i = blockIdx.x * blockDim.x + threadIdx.x;
    if (i >= n) return;
    float v = src[i];
    __nv_bfloat16 h = __float2bfloat16(v);
    hi[i] = h;
    lo[i] = __float2bfloat16(v - __bfloat162float(h));
}

// ---------------- mma.sync bf16x3 GEMM ----------------
// C[M,N] = (Ah+Al)[M,K] @ (Bh+Bl)[N,K]^T, fp32 accumulate.
// CTA tile 128x128, BK=32, 256 thr (8 warps 2m x 4n, warp tile 64x32).
// smem: 2 buffers x 4 tiles (Ah,Al,Bh,Bl) x [128][40] bf16. Requires M%128==0, N%128==0, K%32==0.
#define TPITCH 40                         // padded row pitch (elems): 80B = 5*16B, ldmatrix conflict-free
#define TILE_B (128 * TPITCH * 2)         // bytes per tile (10240)
#define BUF_B  (4 * TILE_B)               // bytes per buffer (40960)

__global__ __launch_bounds__(256) void gemm_mma(const __nv_bfloat16* __restrict__ Ah,
                                                const __nv_bfloat16* __restrict__ Al,
                                                const __nv_bfloat16* __restrict__ Bh,
                                                const __nv_bfloat16* __restrict__ Bl,
                                                float* __restrict__ C, int N, int K) {
    const uint32_t sbase = smem_to_u32(dyn_smem);
    const int t = threadIdx.x, wid = t >> 5, lane = t & 31;
    const int m0 = blockIdx.y * 128, n0 = blockIdx.x * 128;
    const int wm = wid & 1, wn = wid >> 1;          // warp tile: rows wm*64..+64, cols wn*32..+32

    const __nv_bfloat16* srcs[4] = { Ah + (size_t)m0 * K, Al + (size_t)m0 * K,
                                     Bh + (size_t)n0 * K, Bl + (size_t)n0 * K };
    // loader: 512 16B-chunks per tile, 2 per thread
    const int r0c = (t + 0)   >> 2, s0c = (t + 0)   & 3;
    const int r1c = (t + 256) >> 2, s1c = (t + 256) & 3;

    float acc[4][4][4];
    #pragma unroll
    for (int i = 0; i < 4; i++)
        #pragma unroll
        for (int j = 0; j < 4; j++)
            #pragma unroll
            for (int e = 0; e < 4; e++) acc[i][j][e] = 0.f;

    const int NC = K / 32;

    // ldmatrix lane mappings for m16n8k16:
    // A x4: row = (lane&15), col8 = (lane>>4)
    // B x4: row = (lane&7) + ((lane>>4)<<3), col8 = (lane>>3)&1
    const int a_row = lane & 15, a_c8 = lane >> 4;
    const int b_row = (lane & 7) + ((lane >> 4) << 3), b_c8 = (lane >> 3) & 1;

    auto load_chunk = [&](int c, int buf) {
        const int k0 = c * 32;
        uint32_t sb = sbase + buf * BUF_B;
        #pragma unroll
        for (int tile = 0; tile < 4; tile++) {
            const __nv_bfloat16* s = srcs[tile] + k0;
            uint32_t td = sb + tile * TILE_B;
            CP_ASYNC16(td + (uint32_t)(r0c * TPITCH + s0c * 8) * 2, s + (size_t)r0c * K + s0c * 8);
            CP_ASYNC16(td + (uint32_t)(r1c * TPITCH + s1c * 8) * 2, s + (size_t)r1c * K + s1c * 8);
        }
    };

    load_chunk(0, 0);
    CP_COMMIT();

    for (int c = 0; c < NC; c++) {
        if (c + 1 < NC) { load_chunk(c + 1, (c + 1) & 1); CP_COMMIT(); CP_WAIT(1); }
        else            { CP_WAIT(0); }
        __syncthreads();

        const uint32_t sb  = sbase + (c & 1) * BUF_B;
        const uint32_t sAh = sb, sAl = sb + TILE_B, sBh = sb + 2 * TILE_B, sBl = sb + 3 * TILE_B;

        #pragma unroll
        for (int s = 0; s < 2; s++) {                 // two k16 steps per chunk
            const int kc = s * 16;
            uint32_t ah[4][4], al[4][4], bh[4][2], bl[4][2];
            #pragma unroll
            for (int mi = 0; mi < 4; mi++) {
                uint32_t off = (uint32_t)((wm * 64 + mi * 16 + a_row) * TPITCH + kc + a_c8 * 8) * 2;
                ldsm_x4(ah[mi][0], ah[mi][1], ah[mi][2], ah[mi][3], sAh + off);
                ldsm_x4(al[mi][0], al[mi][1], al[mi][2], al[mi][3], sAl + off);
            }
            #pragma unroll
            for (int np = 0; np < 2; np++) {          // each x4 covers two n8 tiles
                uint32_t off = (uint32_t)((wn * 32 + np * 16 + b_row) * TPITCH + kc + b_c8 * 8) * 2;
                uint32_t h0, h1, h2, h3, l0, l1, l2, l3;
                ldsm_x4(h0, h1, h2, h3, sBh + off);
                ldsm_x4(l0, l1, l2, l3, sBl + off);
                bh[np*2][0] = h0; bh[np*2][1] = h1; bh[np*2+1][0] = h2; bh[np*2+1][1] = h3;
                bl[np*2][0] = l0; bl[np*2][1] = l1; bl[np*2+1][0] = l2; bl[np*2+1][1] = l3;
            }
            #pragma unroll
            for (int mi = 0; mi < 4; mi++)
                #pragma unroll
                for (int nj = 0; nj < 4; nj++) {
                    mma16816(acc[mi][nj], ah[mi], bh[nj][0], bh[nj][1]);  // hi*hi
                    mma16816(acc[mi][nj], ah[mi], bl[nj][0], bl[nj][1]);  // hi*lo
                    mma16816(acc[mi][nj], al[mi], bh[nj][0], bh[nj][1]);  // lo*hi
                }
        }
        __syncthreads();
    }

    // epilogue: D frag -> C. thread owns rows (lane/4, lane/4+8), cols 2*(lane%4)..+1 per 16x8 tile
    const int dr = lane >> 2, dc = (lane & 3) * 2;
    #pragma unroll
    for (int mi = 0; mi < 4; mi++) {
        const int row = m0 + wm * 64 + mi * 16 + dr;
        #pragma unroll
        for (int nj = 0; nj < 4; nj++) {
            const int col = n0 + wn * 32 + nj * 8 + dc;
            *(float2*)(C + (size_t)row       * N + col) = make_float2(acc[mi][nj][0], acc[mi][nj][1]);
            *(float2*)(C + (size_t)(row + 8) * N + col) = make_float2(acc[mi][nj][2], acc[mi][nj][3]);
        }
    }
}

// ---------------- RoPE (torch view_as_complex pair layout) ----------------
__global__ void rope_kernel(float* __restrict__ q,
                            const float* __restrict__ cosT,
                            const float* __restrict__ sinT,
                            int rowLen, int nPairs) {
    int idx = blockIdx.x * blockDim.x + threadIdx.x;
    if (idx >= nPairs) return;
    int pairsPerRow = rowLen >> 1;
    int row = idx / pairsPerRow;
    int pr  = idx - row * pairsPerRow;
    int s   = row & (SEQ - 1);
    int p   = pr & 63;
    float c  = cosT[s * 64 + p];
    float sn = sinT[s * 64 + p];
    float2 v = *(float2*)(q + (size_t)row * rowLen + pr * 2);
    float x0 = v.x, x1 = v.y;
    *(float2*)(q + (size_t)row * rowLen + pr * 2) =
        make_float2(x0 * c - x1 * sn, x0 * sn + x1 * c);
}

// ---------------- Flash attention (causal, MQA) — unchanged, known-correct ----------------
__global__ __launch_bounds__(256) void attn_kernel(const float* __restrict__ gq,
                                                   const float* __restrict__ gk,
                                                   const float* __restrict__ gv,
                                                   float* __restrict__ gout) {
    float* smem = (float*)dyn_smem;
    float* sQ = smem;
    float* sK = sQ + 64 * 132;
    float* sV = sK + 64 * 132;
    float* sP = sV + 64 * 132;

    const int b  = blockIdx.z, h = blockIdx.y;
    const int q0 = blockIdx.x * 64;
    const int t  = threadIdx.x, tx = t & 15, ty = t >> 4;
    const float scale = 0.08838834764831845f;

    const float* qbase = gq + ((size_t)b * SEQ + q0) * DMODEL + h * HDIM;
    for (int f = t; f < 2048; f += 256) {
        int r = f >> 5, c4 = (f & 31) << 2;
        *(float4*)&sQ[r * 132 + c4] = *(const float4*)(qbase + (size_t)r * DMODEL + c4);
    }

    float o[4][8];
    float m_i[4], l_i[4];
    #pragma unroll
    for (int i = 0; i < 4; i++) {
        m_i[i] = -1e30f; l_i[i] = 0.f;
        #pragma unroll
        for (int c = 0; c < 8; c++) o[i][c] = 0.f;
    }

    for (int kv0 = 0; kv0 <= q0; kv0 += 64) {
        __syncthreads();
        const float* kb = gk + ((size_t)b * SEQ + kv0) * HDIM;
        const float* vb = gv + ((size_t)b * SEQ + kv0) * HDIM;
        for (int f = t; f < 2048; f += 256) {
            int r = f >> 5, c4 = (f & 31) << 2;
            *(float4*)&sK[r * 132 + c4] = *(const float4*)(kb + (size_t)r * HDIM + c4);
            *(float4*)&sV[r * 132 + c4] = *(const float4*)(vb + (size_t)r * HDIM + c4);
        }
        __syncthreads();

        float sf[4][4] = {};
        #pragma unroll
        for (int d = 0; d < 128; d += 4) {
            float4 a[4], bb[4];
            #pragma unroll
            for (int i = 0; i < 4; i++) a[i]  = *(const float4*)&sQ[(ty*4 + i) * 132 + d];
            #pragma unroll
            for (int j = 0; j < 4; j++) bb[j] = *(const float4*)&sK[(tx*4 + j) * 132 + d];
            #pragma unroll
            for (int i = 0; i < 4; i++)
                #pragma unroll
                for (int j = 0; j < 4; j++)
                    sf[i][j] += a[i].x * bb[j].x + a[i].y * bb[j].y
                              + a[i].z * bb[j].z + a[i].w * bb[j].w;
        }

        const bool diag = (kv0 == q0);
        #pragma unroll
        for (int i = 0; i < 4; i++)
            #pragma unroll
            for (int j = 0; j < 4; j++) {
                float v = sf[i][j] * scale;
                if (diag && (tx*4 + j) > (ty*4 + i)) v = -1e30f;
                sf[i][j] = v;
            }

        #pragma unroll
        for (int i = 0; i < 4; i++) {
            float mt = fmaxf(fmaxf(sf[i][0], sf[i][1]), fmaxf(sf[i][2], sf[i][3]));
            #pragma unroll
            for (int off = 8; off >= 1; off >>= 1)
                mt = fmaxf(mt, __shfl_xor_sync(0xffffffffu, mt, off));
            float mn   = fmaxf(m_i[i], mt);
            float corr = __expf(m_i[i] - mn);
            m_i[i] = mn;
            float sum = 0.f;
            #pragma unroll
            for (int j = 0; j < 4; j++) {
                float p = __expf(sf[i][j] - mn);
                sf[i][j] = p;
                sum += p;
            }
            #pragma unroll
            for (int off = 8; off >= 1; off >>= 1)
                sum += __shfl_xor_sync(0xffffffffu, sum, off);
            l_i[i] = l_i[i] * corr + sum;
            #pragma unroll
            for (int c = 0; c < 8; c++) o[i][c] *= corr;
            *(float4*)&sP[(ty*4 + i) * 68 + tx*4] =
                make_float4(sf[i][0], sf[i][1], sf[i][2], sf[i][3]);
        }
        __syncthreads();

        #pragma unroll 4
        for (int j = 0; j < 64; j += 4) {
            float pr[4][4];
            #pragma unroll
            for (int i = 0; i < 4; i++) {
                float4 pv = *(const float4*)&sP[(ty*4 + i) * 68 + j];
                pr[i][0] = pv.x; pr[i][1] = pv.y; pr[i][2] = pv.z; pr[i][3] = pv.w;
            }
            #pragma unroll
            for (int jj = 0; jj < 4; jj++) {
                float4 v0 = *(const float4*)&sV[(j + jj) * 132 + tx*8];
                float4 v1 = *(const float4*)&sV[(j + jj) * 132 + tx*8 + 4];
                #pragma unroll
                for (int i = 0; i < 4; i++) {
                    float p = pr[i][jj];
                    o[i][0] += p * v0.x; o[i][1] += p * v0.y;
                    o[i][2] += p * v0.z; o[i][3] += p * v0.w;
                    o[i][4] += p * v1.x; o[i][5] += p * v1.y;
                    o[i][6] += p * v1.z; o[i][7] += p * v1.w;
                }
            }
        }
    }

    #pragma unroll
    for (int i = 0; i < 4; i++) {
        float inv = 1.f / l_i[i];
        size_t off = (((size_t)b * SEQ + q0 + ty*4 + i) * NHEAD + h) * HDIM + tx*8;
        *(float4*)(gout + off)     = make_float4(o[i][0]*inv, o[i][1]*inv, o[i][2]*inv, o[i][3]*inv);
        *(float4*)(gout + off + 4) = make_float4(o[i][4]*inv, o[i][5]*inv, o[i][6]*inv, o[i][7]*inv);
    }
}

// ---------------- launch ----------------
extern "C" void kernel_launch(void* const* d_in, const int* in_sizes, int n_in,
                              void* d_out, int out_size) {
    const float* x  = (const float*)d_in[0];
    const float* Wq = (const float*)d_in[1];
    const float* Wk = (const float*)d_in[2];
    const float* Wv = (const float*)d_in[3];
    const float* Wo = (const float*)d_in[4];
    const float* rc = (const float*)d_in[5];
    const float* rs = (const float*)d_in[6];
    float* out = (float*)d_out;

    float *q, *k, *v, *attn;
    cudaGetSymbolAddress((void**)&q,    g_q);
    cudaGetSymbolAddress((void**)&k,    g_k);
    cudaGetSymbolAddress((void**)&v,    g_v);
    cudaGetSymbolAddress((void**)&attn, g_attn);
    __nv_bfloat16 *xh, *xl, *ah, *al, *wqh, *wql, *woh, *wol, *wkh, *wkl, *wvh, *wvl;
    cudaGetSymbolAddress((void**)&xh,  g_xh);  cudaGetSymbolAddress((void**)&xl,  g_xl);
    cudaGetSymbolAddress((void**)&ah,  g_ah);  cudaGetSymbolAddress((void**)&al,  g_al);
    cudaGetSymbolAddress((void**)&wqh, g_wqh); cudaGetSymbolAddress((void**)&wql, g_wql);
    cudaGetSymbolAddress((void**)&woh, g_woh); cudaGetSymbolAddress((void**)&wol, g_wol);
    cudaGetSymbolAddress((void**)&wkh, g_wkh); cudaGetSymbolAddress((void**)&wkl, g_wkl);
    cudaGetSymbolAddress((void**)&wvh, g_wvh); cudaGetSymbolAddress((void**)&wvl, g_wvl);

    const int M = MROWS;                      // 4096
    const int gemmSmem = 2 * BUF_B;           // 81920 bytes
    cudaFuncSetAttribute(gemm_mma, cudaFuncAttributeMaxDynamicSharedMemorySize, gemmSmem);

    // split fp32 -> bf16 hi/lo
    { int n = M * DMODEL;      split_bf16<<<(n + 255) / 256, 256>>>(x,  xh,  xl,  n); }
    { int n = DMODEL * DMODEL; split_bf16<<<(n + 255) / 256, 256>>>(Wq, wqh, wql, n); }
    { int n = HDIM * DMODEL;   split_bf16<<<(n + 255) / 256, 256>>>(Wk, wkh, wkl, n); }
    { int n = HDIM * DMODEL;   split_bf16<<<(n + 255) / 256, 256>>>(Wv, wvh, wvl, n); }
    { int n = DMODEL * DMODEL; split_bf16<<<(n + 255) / 256, 256>>>(Wo, woh, wol, n); }

    // projections on tensor cores (bf16x3 via mma.sync)
    gemm_mma<<<dim3(DMODEL / 128, M / 128), 256, gemmSmem>>>(xh, xl, wqh, wql, q, DMODEL, DMODEL);
    gemm_mma<<<dim3(HDIM   / 128, M / 128), 256, gemmSmem>>>(xh, xl, wkh, wkl, k, HDIM,   DMODEL);
    gemm_mma<<<dim3(HDIM   / 128, M / 128), 256, gemmSmem>>>(xh, xl, wvh, wvl, v, HDIM,   DMODEL);

    // RoPE
    int nPairsQ = M * (DMODEL / 2);
    rope_kernel<<<(nPairsQ + 255) / 256, 256>>>(q, rc, rs, DMODEL, nPairsQ);
    int nPairsK = M * (HDIM / 2);
    rope_kernel<<<(nPairsK + 255) / 256, 256>>>(k, rc, rs, HDIM, nPairsK);

    // flash attention (unchanged)
    const int attnSmem = (3 * 64 * 132 + 64 * 68) * (int)sizeof(float);
    cudaFuncSetAttribute(attn_kernel, cudaFuncAttributeMaxDynamicSharedMemorySize, attnSmem);
    attn_kernel<<<dim3(SEQ / 64, NHEAD, BATCH), 256, attnSmem>>>(q, k, v, attn);

    // output projection (bf16x3 on tensor cores)
    { int n = M * DMODEL; split_bf16<<<(n + 255) / 256, 256>>>(attn, ah, al, n); }
    gemm_mma<<<dim3(DMODEL / 128, M / 128), 256, gemmSmem>>>(ah, al, woh, wol, out, DMODEL, DMODEL);
}

// round 7
// speedup vs baseline: 3.0689x; 2.1874x over previous
#include <cuda_runtime.h>
#include <cuda_bf16.h>
#include <cstdint>

#define SEQ    2048
#define DMODEL 2048
#define NHEAD  16
#define HDIM   128
#define BATCH  2
#define MROWS  (BATCH * SEQ)   // 4096

// single dynamic-smem symbol shared by all kernels
extern __shared__ char dyn_smem[];

// ---------------- scratch (no allocations allowed) ----------------
__device__ float g_q[MROWS * DMODEL];
__device__ float g_k[MROWS * HDIM];
__device__ float g_v[MROWS * HDIM];
__device__ float g_attn[MROWS * DMODEL];

__device__ __nv_bfloat16 g_xh[MROWS * DMODEL],  g_xl[MROWS * DMODEL];
__device__ __nv_bfloat16 g_ah[MROWS * DMODEL],  g_al[MROWS * DMODEL];
__device__ __nv_bfloat16 g_wqh[DMODEL * DMODEL], g_wql[DMODEL * DMODEL];
__device__ __nv_bfloat16 g_woh[DMODEL * DMODEL], g_wol[DMODEL * DMODEL];
__device__ __nv_bfloat16 g_wkh[HDIM * DMODEL],   g_wkl[HDIM * DMODEL];
__device__ __nv_bfloat16 g_wvh[HDIM * DMODEL],   g_wvl[HDIM * DMODEL];
// attention operands (RoPE'd, bf16 hi/lo)
__device__ __nv_bfloat16 g_qbh[MROWS * DMODEL], g_qbl[MROWS * DMODEL];
__device__ __nv_bfloat16 g_kbh[MROWS * HDIM],   g_kbl[MROWS * HDIM];
__device__ __nv_bfloat16 g_vbh[MROWS * HDIM],   g_vbl[MROWS * HDIM];

// ---------------- helpers ----------------
__device__ __forceinline__ uint32_t smem_to_u32(const void* p) {
    uint32_t a;
    asm("{ .reg .u64 t; cvta.to.shared.u64 t, %1; cvt.u32.u64 %0, t; }" : "=r"(a) : "l"(p));
    return a;
}

#define CP_ASYNC16(saddr, gptr) \
    asm volatile("cp.async.cg.shared.global [%0], [%1], 16;" :: "r"(saddr), "l"(gptr))
#define CP_COMMIT() asm volatile("cp.async.commit_group;" ::: "memory")
#define CP_WAIT(n)  asm volatile("cp.async.wait_group %0;" :: "n"(n) : "memory")

__device__ __forceinline__ void ldsm_x4(uint32_t& r0, uint32_t& r1, uint32_t& r2, uint32_t& r3,
                                        uint32_t addr) {
    asm volatile("ldmatrix.sync.aligned.m8n8.x4.shared.b16 {%0,%1,%2,%3}, [%4];"
                 : "=r"(r0), "=r"(r1), "=r"(r2), "=r"(r3) : "r"(addr));
}
__device__ __forceinline__ void ldsm_x4t(uint32_t& r0, uint32_t& r1, uint32_t& r2, uint32_t& r3,
                                         uint32_t addr) {
    asm volatile("ldmatrix.sync.aligned.m8n8.x4.trans.shared.b16 {%0,%1,%2,%3}, [%4];"
                 : "=r"(r0), "=r"(r1), "=r"(r2), "=r"(r3) : "r"(addr));
}
__device__ __forceinline__ void mma16816(float* d, const uint32_t* a, uint32_t b0, uint32_t b1) {
    asm volatile(
        "mma.sync.aligned.m16n8k16.row.col.f32.bf16.bf16.f32 "
        "{%0,%1,%2,%3}, {%4,%5,%6,%7}, {%8,%9}, {%0,%1,%2,%3};"
        : "+f"(d[0]), "+f"(d[1]), "+f"(d[2]), "+f"(d[3])
        : "r"(a[0]), "r"(a[1]), "r"(a[2]), "r"(a[3]), "r"(b0), "r"(b1));
}
// pack two f32 -> bf16x2 (lo = first element / lower k index)
__device__ __forceinline__ uint32_t pack_bf16(float lo, float hi) {
    uint32_t r;
    asm("cvt.rn.bf16x2.f32 %0, %1, %2;" : "=r"(r) : "f"(hi), "f"(lo));
    return r;
}

// ---------------- fp32 -> bf16 hi/lo split ----------------
__global__ void split_bf16(const float* __restrict__ src,
                           __nv_bfloat16* __restrict__ hi,
                           __nv_bfloat16* __restrict__ lo, int n) {
    int i = blockIdx.x * blockDim.x + threadIdx.x;
    if (i >= n) return;
    float v = src[i];
    __nv_bfloat16 h = __float2bfloat16(v);
    hi[i] = h;
    lo[i] = __float2bfloat16(v - __bfloat162float(h));
}

// ---------------- RoPE fused with bf16 hi/lo split ----------------
__global__ void rope_split(const float* __restrict__ src,
                           __nv_bfloat16* __restrict__ hi,
                           __nv_bfloat16* __restrict__ lo,
                           const float* __restrict__ cosT,
                           const float* __restrict__ sinT,
                           int rowLen, int nPairs) {
    int idx = blockIdx.x * blockDim.x + threadIdx.x;
    if (idx >= nPairs) return;
    int pairsPerRow = rowLen >> 1;
    int row = idx / pairsPerRow;
    int pr  = idx - row * pairsPerRow;
    int s   = row & (SEQ - 1);
    int p   = pr & 63;
    float c  = cosT[s * 64 + p];
    float sn = sinT[s * 64 + p];
    float2 v = *(const float2*)(src + (size_t)row * rowLen + pr * 2);
    float o0 = v.x * c - v.y * sn;
    float o1 = v.x * sn + v.y * c;
    __nv_bfloat16 h0 = __float2bfloat16(o0), h1 = __float2bfloat16(o1);
    *(__nv_bfloat162*)(hi + (size_t)row * rowLen + pr * 2) = __nv_bfloat162(h0, h1);
    *(__nv_bfloat162*)(lo + (size_t)row * rowLen + pr * 2) =
        __nv_bfloat162(__float2bfloat16(o0 - __bfloat162float(h0)),
                       __float2bfloat16(o1 - __bfloat162float(h1)));
}

// ---------------- mma.sync bf16x3 GEMM (unchanged, validated R5) ----------------
#define TPITCH 40
#define TILE_B (128 * TPITCH * 2)
#define BUF_B  (4 * TILE_B)

__global__ __launch_bounds__(256) void gemm_mma(const __nv_bfloat16* __restrict__ Ah,
                                                const __nv_bfloat16* __restrict__ Al,
                                                const __nv_bfloat16* __restrict__ Bh,
                                                const __nv_bfloat16* __restrict__ Bl,
                                                float* __restrict__ C, int N, int K) {
    const uint32_t sbase = smem_to_u32(dyn_smem);
    const int t = threadIdx.x, wid = t >> 5, lane = t & 31;
    const int m0 = blockIdx.y * 128, n0 = blockIdx.x * 128;
    const int wm = wid & 1, wn = wid >> 1;

    const __nv_bfloat16* srcs[4] = { Ah + (size_t)m0 * K, Al + (size_t)m0 * K,
                                     Bh + (size_t)n0 * K, Bl + (size_t)n0 * K };
    const int r0c = (t + 0)   >> 2, s0c = (t + 0)   & 3;
    const int r1c = (t + 256) >> 2, s1c = (t + 256) & 3;

    float acc[4][4][4];
    #pragma unroll
    for (int i = 0; i < 4; i++)
        #pragma unroll
        for (int j = 0; j < 4; j++)
            #pragma unroll
            for (int e = 0; e < 4; e++) acc[i][j][e] = 0.f;

    const int NC = K / 32;
    const int a_row = lane & 15, a_c8 = lane >> 4;
    const int b_row = (lane & 7) + ((lane >> 4) << 3), b_c8 = (lane >> 3) & 1;

    auto load_chunk = [&](int c, int buf) {
        const int k0 = c * 32;
        uint32_t sb = sbase + buf * BUF_B;
        #pragma unroll
        for (int tile = 0; tile < 4; tile++) {
            const __nv_bfloat16* s = srcs[tile] + k0;
            uint32_t td = sb + tile * TILE_B;
            CP_ASYNC16(td + (uint32_t)(r0c * TPITCH + s0c * 8) * 2, s + (size_t)r0c * K + s0c * 8);
            CP_ASYNC16(td + (uint32_t)(r1c * TPITCH + s1c * 8) * 2, s + (size_t)r1c * K + s1c * 8);
        }
    };

    load_chunk(0, 0);
    CP_COMMIT();

    for (int c = 0; c < NC; c++) {
        if (c + 1 < NC) { load_chunk(c + 1, (c + 1) & 1); CP_COMMIT(); CP_WAIT(1); }
        else            { CP_WAIT(0); }
        __syncthreads();

        const uint32_t sb  = sbase + (c & 1) * BUF_B;
        const uint32_t sAh = sb, sAl = sb + TILE_B, sBh = sb + 2 * TILE_B, sBl = sb + 3 * TILE_B;

        #pragma unroll
        for (int s = 0; s < 2; s++) {
            const int kc = s * 16;
            uint32_t ah[4][4], al[4][4], bh[4][2], bl[4][2];
            #pragma unroll
            for (int mi = 0; mi < 4; mi++) {
                uint32_t off = (uint32_t)((wm * 64 + mi * 16 + a_row) * TPITCH + kc + a_c8 * 8) * 2;
                ldsm_x4(ah[mi][0], ah[mi][1], ah[mi][2], ah[mi][3], sAh + off);
                ldsm_x4(al[mi][0], al[mi][1], al[mi][2], al[mi][3], sAl + off);
            }
            #pragma unroll
            for (int np = 0; np < 2; np++) {
                uint32_t off = (uint32_t)((wn * 32 + np * 16 + b_row) * TPITCH + kc + b_c8 * 8) * 2;
                uint32_t h0, h1, h2, h3, l0, l1, l2, l3;
                ldsm_x4(h0, h1, h2, h3, sBh + off);
                ldsm_x4(l0, l1, l2, l3, sBl + off);
                bh[np*2][0] = h0; bh[np*2][1] = h1; bh[np*2+1][0] = h2; bh[np*2+1][1] = h3;
                bl[np*2][0] = l0; bl[np*2][1] = l1; bl[np*2+1][0] = l2; bl[np*2+1][1] = l3;
            }
            #pragma unroll
            for (int mi = 0; mi < 4; mi++)
                #pragma unroll
                for (int nj = 0; nj < 4; nj++) {
                    mma16816(acc[mi][nj], ah[mi], bh[nj][0], bh[nj][1]);
                    mma16816(acc[mi][nj], ah[mi], bl[nj][0], bl[nj][1]);
                    mma16816(acc[mi][nj], al[mi], bh[nj][0], bh[nj][1]);
                }
        }
        __syncthreads();
    }

    const int dr = lane >> 2, dc = (lane & 3) * 2;
    #pragma unroll
    for (int mi = 0; mi < 4; mi++) {
        const int row = m0 + wm * 64 + mi * 16 + dr;
        #pragma unroll
        for (int nj = 0; nj < 4; nj++) {
            const int col = n0 + wn * 32 + nj * 8 + dc;
            *(float2*)(C + (size_t)row       * N + col) = make_float2(acc[mi][nj][0], acc[mi][nj][1]);
            *(float2*)(C + (size_t)(row + 8) * N + col) = make_float2(acc[mi][nj][2], acc[mi][nj][3]);
        }
    }
}

// ---------------- tensor-core flash attention (causal, MQA, bf16x3) ----------------
// CTA: 128 q rows for one (b,h). 8 warps x 16 q rows. KV tiles of 64, double-buffered.
// smem rows padded to 136 elems (272B = 17 x 16B chunks -> ldmatrix conflict-free).
#define QP    136
#define QPB   (QP * 2)            // 272 bytes/row
#define ATT_SQH 0
#define ATT_SQL (128 * QPB)       // 34816
#define ATT_KV0 (2 * 128 * QPB)   // 69632
#define KVT   (64 * QPB)          // 17408
#define KVBUF (4 * KVT)           // 69632 : Kh, Kl, Vh, Vl
#define ATT_SMEM (ATT_KV0 + 2 * KVBUF)   // 208896

__global__ __launch_bounds__(256) void attn_mma(
    const __nv_bfloat16* __restrict__ Qh, const __nv_bfloat16* __restrict__ Ql,
    const __nv_bfloat16* __restrict__ Kh, const __nv_bfloat16* __restrict__ Kl,
    const __nv_bfloat16* __restrict__ Vh, const __nv_bfloat16* __restrict__ Vl,
    float* __restrict__ Out) {
    const uint32_t sb = smem_to_u32(dyn_smem);
    const int t = threadIdx.x, w = t >> 5, lane = t & 31;
    const int b = blockIdx.z, h = blockIdx.y;
    const int q0 = blockIdx.x * 128;
    const int nt = q0 / 64 + 2;                 // KV tiles needed (causal)
    const float scale = 0.08838834764831845f;   // 1/sqrt(128)

    // frag address components (validated in gemm_mma)
    const int a_row = lane & 15, a_c8 = lane >> 4;                       // A (Q, non-trans)
    const int kb_row = (lane & 7) + ((lane >> 4) << 3);                  // B (K, non-trans)
    const int kb_c8 = (lane >> 3) & 1;
    const int v_row = (lane & 7) + (((lane >> 3) & 1) << 3);             // B (V, trans)
    const int v_c8 = lane >> 4;
    const int dr = lane >> 2, dc = (lane & 3) * 2;

    // ---- load Q tile (hi+lo) via cp.async ----
    {
        const __nv_bfloat16* qsrc[2] = { Qh, Ql };
        #pragma unroll
        for (int half = 0; half < 2; half++) {
            uint32_t dst = sb + (half ? ATT_SQL : ATT_SQH);
            const __nv_bfloat16* s = qsrc[half] + ((size_t)(b * SEQ + q0)) * DMODEL + h * HDIM;
            #pragma unroll
            for (int it = 0; it < 8; it++) {
                int idx = t + it * 256;          // 0..2047 (128 rows x 16 chunks)
                int row = idx >> 4, c = idx & 15;
                CP_ASYNC16(dst + (uint32_t)(row * QPB + c * 16), s + (size_t)row * DMODEL + c * 8);
            }
        }
    }
    auto load_kv = [&](int tile, int buf) {
        const int kv0 = tile * 64;
        const size_t base = (size_t)(b * SEQ + kv0) * HDIM;
        const __nv_bfloat16* srcs[4] = { Kh + base, Kl + base, Vh + base, Vl + base };
        uint32_t bb = sb + ATT_KV0 + buf * KVBUF;
        #pragma unroll
        for (int part = 0; part < 4; part++) {
            #pragma unroll
            for (int it = 0; it < 4; it++) {
                int idx = t + it * 256;          // 0..1023 (64 rows x 16 chunks)
                int row = idx >> 4, c = idx & 15;
                CP_ASYNC16(bb + (uint32_t)(part * KVT + row * QPB + c * 16),
                           srcs[part] + (size_t)row * HDIM + c * 8);
            }
        }
    };
    load_kv(0, 0);
    CP_COMMIT();                                 // group0 = Q + KV0

    float o[16][4];
    #pragma unroll
    for (int nj = 0; nj < 16; nj++)
        #pragma unroll
        for (int e = 0; e < 4; e++) o[nj][e] = 0.f;
    float m0 = -1e30f, m1 = -1e30f, l0 = 0.f, l1 = 0.f;
    const int row0 = q0 + w * 16 + dr, row1 = row0 + 8;

    for (int tt = 0; tt < nt; tt++) {
        if (tt + 1 < nt) { load_kv(tt + 1, (tt + 1) & 1); CP_COMMIT(); CP_WAIT(1); }
        else             { CP_WAIT(0); }
        __syncthreads();

        const int kv0 = tt * 64;
        const uint32_t bKh = sb + ATT_KV0 + (tt & 1) * KVBUF;
        const uint32_t bKl = bKh + KVT, bVh = bKh + 2 * KVT, bVl = bKh + 3 * KVT;
        const uint32_t bQh = sb + ATT_SQH, bQl = sb + ATT_SQL;

        // ---- S = Q K^T (bf16x3) ----
        float s[8][4];
        #pragma unroll
        for (int nj = 0; nj < 8; nj++)
            #pragma unroll
            for (int e = 0; e < 4; e++) s[nj][e] = 0.f;

        #pragma unroll
        for (int k = 0; k < 8; k++) {
            uint32_t qoff = (uint32_t)((w * 16 + a_row) * QPB + (k * 16 + a_c8 * 8) * 2);
            uint32_t ah[4], al[4];
            ldsm_x4(ah[0], ah[1], ah[2], ah[3], bQh + qoff);
            ldsm_x4(al[0], al[1], al[2], al[3], bQl + qoff);
            #pragma unroll
            for (int np = 0; np < 4; np++) {
                uint32_t koff = (uint32_t)((np * 16 + kb_row) * QPB + (k * 16 + kb_c8 * 8) * 2);
                uint32_t h0, h1, h2, h3, lo0, lo1, lo2, lo3;
                ldsm_x4(h0, h1, h2, h3, bKh + koff);
                ldsm_x4(lo0, lo1, lo2, lo3, bKl + koff);
                mma16816(s[2*np],     ah, h0, h1);
                mma16816(s[2*np],     ah, lo0, lo1);
                mma16816(s[2*np],     al, h0, h1);
                mma16816(s[2*np + 1], ah, h2, h3);
                mma16816(s[2*np + 1], ah, lo2, lo3);
                mma16816(s[2*np + 1], al, h2, h3);
            }
        }

        // ---- scale + causal mask ----
        const bool domask = (kv0 + 63 > q0);
        #pragma unroll
        for (int nj = 0; nj < 8; nj++) {
            #pragma unroll
            for (int e = 0; e < 4; e++) s[nj][e] *= scale;
            if (domask) {
                int cg = kv0 + nj * 8 + dc;
                if (cg     > row0) s[nj][0] = -1e30f;
                if (cg + 1 > row0) s[nj][1] = -1e30f;
                if (cg     > row1) s[nj][2] = -1e30f;
                if (cg + 1 > row1) s[nj][3] = -1e30f;
            }
        }

        // ---- online softmax (rows row0, row1; domain = lane quad) ----
        float mx0 = -1e30f, mx1 = -1e30f;
        #pragma unroll
        for (int nj = 0; nj < 8; nj++) {
            mx0 = fmaxf(mx0, fmaxf(s[nj][0], s[nj][1]));
            mx1 = fmaxf(mx1, fmaxf(s[nj][2], s[nj][3]));
        }
        mx0 = fmaxf(mx0, __shfl_xor_sync(0xffffffffu, mx0, 1));
        mx0 = fmaxf(mx0, __shfl_xor_sync(0xffffffffu, mx0, 2));
        mx1 = fmaxf(mx1, __shfl_xor_sync(0xffffffffu, mx1, 1));
        mx1 = fmaxf(mx1, __shfl_xor_sync(0xffffffffu, mx1, 2));
        float mn0 = fmaxf(m0, mx0), mn1 = fmaxf(m1, mx1);
        float c0 = __expf(m0 - mn0), c1 = __expf(m1 - mn1);
        float sum0 = 0.f, sum1 = 0.f;
        #pragma unroll
        for (int nj = 0; nj < 8; nj++) {
            s[nj][0] = __expf(s[nj][0] - mn0); sum0 += s[nj][0];
            s[nj][1] = __expf(s[nj][1] - mn0); sum0 += s[nj][1];
            s[nj][2] = __expf(s[nj][2] - mn1); sum1 += s[nj][2];
            s[nj][3] = __expf(s[nj][3] - mn1); sum1 += s[nj][3];
        }
        sum0 += __shfl_xor_sync(0xffffffffu, sum0, 1);
        sum0 += __shfl_xor_sync(0xffffffffu, sum0, 2);
        sum1 += __shfl_xor_sync(0xffffffffu, sum1, 1);
        sum1 += __shfl_xor_sync(0xffffffffu, sum1, 2);
        l0 = l0 * c0 + sum0; l1 = l1 * c1 + sum1;
        m0 = mn0; m1 = mn1;
        #pragma unroll
        for (int nj = 0; nj < 16; nj++) {
            o[nj][0] *= c0; o[nj][1] *= c0;
            o[nj][2] *= c1; o[nj][3] *= c1;
        }

        // ---- O += P V (bf16x3; P split hi/lo in registers) ----
        #pragma unroll
        for (int kq = 0; kq < 4; kq++) {
            // A-frags from S tiles 2kq, 2kq+1 (C-layout == A-layout)
            float ph[8], pl[8];
            #pragma unroll
            for (int e = 0; e < 4; e++) {
                float p0 = s[2*kq][e], p1 = s[2*kq + 1][e];
                __nv_bfloat16 h0 = __float2bfloat16(p0), h1 = __float2bfloat16(p1);
                ph[e]     = __bfloat162float(h0); pl[e]     = p0 - ph[e];
                ph[4 + e] = __bfloat162float(h1); pl[4 + e] = p1 - ph[4 + e];
            }
            uint32_t pah[4], pal[4];
            pah[0] = pack_bf16(ph[0], ph[1]); pah[1] = pack_bf16(ph[2], ph[3]);
            pah[2] = pack_bf16(ph[4], ph[5]); pah[3] = pack_bf16(ph[6], ph[7]);
            pal[0] = pack_bf16(pl[0], pl[1]); pal[1] = pack_bf16(pl[2], pl[3]);
            pal[2] = pack_bf16(pl[4], pl[5]); pal[3] = pack_bf16(pl[6], pl[7]);

            #pragma unroll
            for (int np = 0; np < 8; np++) {
                uint32_t voff = (uint32_t)((kq * 16 + v_row) * QPB + (np * 16 + v_c8 * 8) * 2);
                uint32_t h0, h1, h2, h3, lo0, lo1, lo2, lo3;
                ldsm_x4t(h0, h1, h2, h3, bVh + voff);
                ldsm_x4t(lo0, lo1, lo2, lo3, bVl + voff);
                mma16816(o[2*np],     pah, h0, h1);
                mma16816(o[2*np],     pah, lo0, lo1);
                mma16816(o[2*np],     pal, h0, h1);
                mma16816(o[2*np + 1], pah, h2, h3);
                mma16816(o[2*np + 1], pah, lo2, lo3);
                mma16816(o[2*np + 1], pal, h2, h3);
            }
        }
        __syncthreads();   // all reads of buf (tt&1) done before next iter overwrites it
    }

    // ---- epilogue: normalize, write [B,S,D] ----
    const float inv0 = 1.f / l0, inv1 = 1.f / l1;
    const size_t ob0 = (size_t)(b * SEQ + row0) * DMODEL + h * HDIM;
    const size_t ob1 = (size_t)(b * SEQ + row1) * DMODEL + h * HDIM;
    #pragma unroll
    for (int nj = 0; nj < 16; nj++) {
        *(float2*)(Out + ob0 + nj * 8 + dc) = make_float2(o[nj][0] * inv0, o[nj][1] * inv0);
        *(float2*)(Out + ob1 + nj * 8 + dc) = make_float2(o[nj][2] * inv1, o[nj][3] * inv1);
    }
}

// ---------------- launch ----------------
extern "C" void kernel_launch(void* const* d_in, const int* in_sizes, int n_in,
                              void* d_out, int out_size) {
    const float* x  = (const float*)d_in[0];
    const float* Wq = (const float*)d_in[1];
    const float* Wk = (const float*)d_in[2];
    const float* Wv = (const float*)d_in[3];
    const float* Wo = (const float*)d_in[4];
    const float* rc = (const float*)d_in[5];
    const float* rs = (const float*)d_in[6];
    float* out = (float*)d_out;

    float *q, *k, *v, *attn;
    cudaGetSymbolAddress((void**)&q,    g_q);
    cudaGetSymbolAddress((void**)&k,    g_k);
    cudaGetSymbolAddress((void**)&v,    g_v);
    cudaGetSymbolAddress((void**)&attn, g_attn);
    __nv_bfloat16 *xh, *xl, *ah, *al, *wqh, *wql, *woh, *wol, *wkh, *wkl, *wvh, *wvl;
    __nv_bfloat16 *qbh, *qbl, *kbh, *kbl, *vbh, *vbl;
    cudaGetSymbolAddress((void**)&xh,  g_xh);  cudaGetSymbolAddress((void**)&xl,  g_xl);
    cudaGetSymbolAddress((void**)&ah,  g_ah);  cudaGetSymbolAddress((void**)&al,  g_al);
    cudaGetSymbolAddress((void**)&wqh, g_wqh); cudaGetSymbolAddress((void**)&wql, g_wql);
    cudaGetSymbolAddress((void**)&woh, g_woh); cudaGetSymbolAddress((void**)&wol, g_wol);
    cudaGetSymbolAddress((void**)&wkh, g_wkh); cudaGetSymbolAddress((void**)&wkl, g_wkl);
    cudaGetSymbolAddress((void**)&wvh, g_wvh); cudaGetSymbolAddress((void**)&wvl, g_wvl);
    cudaGetSymbolAddress((void**)&qbh, g_qbh); cudaGetSymbolAddress((void**)&qbl, g_qbl);
    cudaGetSymbolAddress((void**)&kbh, g_kbh); cudaGetSymbolAddress((void**)&kbl, g_kbl);
    cudaGetSymbolAddress((void**)&vbh, g_vbh); cudaGetSymbolAddress((void**)&vbl, g_vbl);

    const int M = MROWS;
    const int gemmSmem = 2 * BUF_B;
    cudaFuncSetAttribute(gemm_mma, cudaFuncAttributeMaxDynamicSharedMemorySize, gemmSmem);
    cudaFuncSetAttribute(attn_mma, cudaFuncAttributeMaxDynamicSharedMemorySize, ATT_SMEM);

    // split fp32 -> bf16 hi/lo
    { int n = M * DMODEL;      split_bf16<<<(n + 255) / 256, 256>>>(x,  xh,  xl,  n); }
    { int n = DMODEL * DMODEL; split_bf16<<<(n + 255) / 256, 256>>>(Wq, wqh, wql, n); }
    { int n = HDIM * DMODEL;   split_bf16<<<(n + 255) / 256, 256>>>(Wk, wkh, wkl, n); }
    { int n = HDIM * DMODEL;   split_bf16<<<(n + 255) / 256, 256>>>(Wv, wvh, wvl, n); }
    { int n = DMODEL * DMODEL; split_bf16<<<(n + 255) / 256, 256>>>(Wo, woh, wol, n); }

    // projections (bf16x3 mma.sync)
    gemm_mma<<<dim3(DMODEL / 128, M / 128), 256, gemmSmem>>>(xh, xl, wqh, wql, q, DMODEL, DMODEL);
    gemm_mma<<<dim3(HDIM   / 128, M / 128), 256, gemmSmem>>>(xh, xl, wkh, wkl, k, HDIM,   DMODEL);
    gemm_mma<<<dim3(HDIM   / 128, M / 128), 256, gemmSmem>>>(xh, xl, wvh, wvl, v, HDIM,   DMODEL);

    // RoPE fused with bf16 split; V plain split
    { int n = M * (DMODEL / 2); rope_split<<<(n + 255) / 256, 256>>>(q, qbh, qbl, rc, rs, DMODEL, n); }
    { int n = M * (HDIM / 2);   rope_split<<<(n + 255) / 256, 256>>>(k, kbh, kbl, rc, rs, HDIM,   n); }
    { int n = M * HDIM;         split_bf16<<<(n + 255) / 256, 256>>>(v, vbh, vbl, n); }

    // tensor-core flash attention
    attn_mma<<<dim3(SEQ / 128, NHEAD, BATCH), 256, ATT_SMEM>>>(qbh, qbl, kbh, kbl, vbh, vbl, attn);

    // output projection
    { int n = M * DMODEL; split_bf16<<<(n + 255) / 256, 256>>>(attn, ah, al, n); }
    gemm_mma<<<dim3(DMODEL / 128, M / 128), 256, gemmSmem>>>(ah, al, woh, wol, out, DMODEL, DMODEL);
}

// round 8
// speedup vs baseline: 3.2173x; 1.0484x over previous
#include <cuda_runtime.h>
#include <cuda_bf16.h>
#include <cstdint>

#define SEQ    2048
#define DMODEL 2048
#define NHEAD  16
#define HDIM   128
#define BATCH  2
#define MROWS  (BATCH * SEQ)   // 4096

extern __shared__ char dyn_smem[];

// ---------------- scratch (no allocations allowed) ----------------
__device__ __nv_bfloat16 g_xh[MROWS * DMODEL],  g_xl[MROWS * DMODEL];
__device__ __nv_bfloat16 g_ah[MROWS * DMODEL],  g_al[MROWS * DMODEL];
__device__ __nv_bfloat16 g_wqh[DMODEL * DMODEL], g_wql[DMODEL * DMODEL];
__device__ __nv_bfloat16 g_woh[DMODEL * DMODEL], g_wol[DMODEL * DMODEL];
__device__ __nv_bfloat16 g_wkh[HDIM * DMODEL],   g_wkl[HDIM * DMODEL];
__device__ __nv_bfloat16 g_wvh[HDIM * DMODEL],   g_wvl[HDIM * DMODEL];
// attention operands (RoPE'd, bf16 hi/lo) — written directly by GEMM epilogues
__device__ __nv_bfloat16 g_qbh[MROWS * DMODEL], g_qbl[MROWS * DMODEL];
__device__ __nv_bfloat16 g_kbh[MROWS * HDIM],   g_kbl[MROWS * HDIM];
__device__ __nv_bfloat16 g_vbh[MROWS * HDIM],   g_vbl[MROWS * HDIM];

// ---------------- helpers ----------------
__device__ __forceinline__ uint32_t smem_to_u32(const void* p) {
    uint32_t a;
    asm("{ .reg .u64 t; cvta.to.shared.u64 t, %1; cvt.u32.u64 %0, t; }" : "=r"(a) : "l"(p));
    return a;
}

#define CP_ASYNC16(saddr, gptr) \
    asm volatile("cp.async.cg.shared.global [%0], [%1], 16;" :: "r"(saddr), "l"(gptr))
#define CP_COMMIT() asm volatile("cp.async.commit_group;" ::: "memory")
#define CP_WAIT(n)  asm volatile("cp.async.wait_group %0;" :: "n"(n) : "memory")

__device__ __forceinline__ void ldsm_x4(uint32_t& r0, uint32_t& r1, uint32_t& r2, uint32_t& r3,
                                        uint32_t addr) {
    asm volatile("ldmatrix.sync.aligned.m8n8.x4.shared.b16 {%0,%1,%2,%3}, [%4];"
                 : "=r"(r0), "=r"(r1), "=r"(r2), "=r"(r3) : "r"(addr));
}
__device__ __forceinline__ void ldsm_x4t(uint32_t& r0, uint32_t& r1, uint32_t& r2, uint32_t& r3,
                                         uint32_t addr) {
    asm volatile("ldmatrix.sync.aligned.m8n8.x4.trans.shared.b16 {%0,%1,%2,%3}, [%4];"
                 : "=r"(r0), "=r"(r1), "=r"(r2), "=r"(r3) : "r"(addr));
}
__device__ __forceinline__ void mma16816(float* d, const uint32_t* a, uint32_t b0, uint32_t b1) {
    asm volatile(
        "mma.sync.aligned.m16n8k16.row.col.f32.bf16.bf16.f32 "
        "{%0,%1,%2,%3}, {%4,%5,%6,%7}, {%8,%9}, {%0,%1,%2,%3};"
        : "+f"(d[0]), "+f"(d[1]), "+f"(d[2]), "+f"(d[3])
        : "r"(a[0]), "r"(a[1]), "r"(a[2]), "r"(a[3]), "r"(b0), "r"(b1));
}
__device__ __forceinline__ uint32_t pack_bf16(float lo, float hi) {
    uint32_t r;
    asm("cvt.rn.bf16x2.f32 %0, %1, %2;" : "=r"(r) : "f"(hi), "f"(lo));
    return r;
}
// split one f32 into bf16 hi + residual lo, return packed pair writer helpers
__device__ __forceinline__ void split1(float v, float& h, float& l) {
    __nv_bfloat16 hb = __float2bfloat16(v);
    h = __bfloat162float(hb);
    l = v - h;
}

// ---------------- fp32 -> bf16 hi/lo split (inputs/weights only) ----------------
__global__ void split_bf16(const float* __restrict__ src,
                           __nv_bfloat16* __restrict__ hi,
                           __nv_bfloat16* __restrict__ lo, int n) {
    int i = blockIdx.x * blockDim.x + threadIdx.x;
    if (i >= n) return;
    float v = src[i];
    __nv_bfloat16 h = __float2bfloat16(v);
    hi[i] = h;
    lo[i] = __float2bfloat16(v - __bfloat162float(h));
}

// ---------------- mma.sync bf16x3 GEMM with fused epilogues ----------------
// MODE 0: write fp32 C.  MODE 1: RoPE (pair cols) + hi/lo bf16 split.  MODE 2: hi/lo split.
#define TPITCH 40
#define TILE_B (128 * TPITCH * 2)
#define BUF_B  (4 * TILE_B)

template <int MODE>
__global__ __launch_bounds__(256) void gemm_mma(const __nv_bfloat16* __restrict__ Ah,
                                                const __nv_bfloat16* __restrict__ Al,
                                                const __nv_bfloat16* __restrict__ Bh,
                                                const __nv_bfloat16* __restrict__ Bl,
                                                float* __restrict__ C,
                                                __nv_bfloat16* __restrict__ Ohi,
                                                __nv_bfloat16* __restrict__ Olo,
                                                const float* __restrict__ cosT,
                                                const float* __restrict__ sinT,
                                                int N, int K) {
    const uint32_t sbase = smem_to_u32(dyn_smem);
    const int t = threadIdx.x, wid = t >> 5, lane = t & 31;
    const int m0 = blockIdx.y * 128, n0 = blockIdx.x * 128;
    const int wm = wid & 1, wn = wid >> 1;

    const __nv_bfloat16* srcs[4] = { Ah + (size_t)m0 * K, Al + (size_t)m0 * K,
                                     Bh + (size_t)n0 * K, Bl + (size_t)n0 * K };
    const int r0c = (t + 0)   >> 2, s0c = (t + 0)   & 3;
    const int r1c = (t + 256) >> 2, s1c = (t + 256) & 3;

    float acc[4][4][4];
    #pragma unroll
    for (int i = 0; i < 4; i++)
        #pragma unroll
        for (int j = 0; j < 4; j++)
            #pragma unroll
            for (int e = 0; e < 4; e++) acc[i][j][e] = 0.f;

    const int NC = K / 32;
    const int a_row = lane & 15, a_c8 = lane >> 4;
    const int b_row = (lane & 7) + ((lane >> 4) << 3), b_c8 = (lane >> 3) & 1;

    auto load_chunk = [&](int c, int buf) {
        const int k0 = c * 32;
        uint32_t sb = sbase + buf * BUF_B;
        #pragma unroll
        for (int tile = 0; tile < 4; tile++) {
            const __nv_bfloat16* s = srcs[tile] + k0;
            uint32_t td = sb + tile * TILE_B;
            CP_ASYNC16(td + (uint32_t)(r0c * TPITCH + s0c * 8) * 2, s + (size_t)r0c * K + s0c * 8);
            CP_ASYNC16(td + (uint32_t)(r1c * TPITCH + s1c * 8) * 2, s + (size_t)r1c * K + s1c * 8);
        }
    };

    load_chunk(0, 0);
    CP_COMMIT();

    for (int c = 0; c < NC; c++) {
        if (c + 1 < NC) { load_chunk(c + 1, (c + 1) & 1); CP_COMMIT(); CP_WAIT(1); }
        else            { CP_WAIT(0); }
        __syncthreads();

        const uint32_t sb  = sbase + (c & 1) * BUF_B;
        const uint32_t sAh = sb, sAl = sb + TILE_B, sBh = sb + 2 * TILE_B, sBl = sb + 3 * TILE_B;

        #pragma unroll
        for (int s = 0; s < 2; s++) {
            const int kc = s * 16;
            uint32_t ah[4][4], al[4][4], bh[4][2], bl[4][2];
            #pragma unroll
            for (int mi = 0; mi < 4; mi++) {
                uint32_t off = (uint32_t)((wm * 64 + mi * 16 + a_row) * TPITCH + kc + a_c8 * 8) * 2;
                ldsm_x4(ah[mi][0], ah[mi][1], ah[mi][2], ah[mi][3], sAh + off);
                ldsm_x4(al[mi][0], al[mi][1], al[mi][2], al[mi][3], sAl + off);
            }
            #pragma unroll
            for (int np = 0; np < 2; np++) {
                uint32_t off = (uint32_t)((wn * 32 + np * 16 + b_row) * TPITCH + kc + b_c8 * 8) * 2;
                uint32_t h0, h1, h2, h3, l0, l1, l2, l3;
                ldsm_x4(h0, h1, h2, h3, sBh + off);
                ldsm_x4(l0, l1, l2, l3, sBl + off);
                bh[np*2][0] = h0; bh[np*2][1] = h1; bh[np*2+1][0] = h2; bh[np*2+1][1] = h3;
                bl[np*2][0] = l0; bl[np*2][1] = l1; bl[np*2+1][0] = l2; bl[np*2+1][1] = l3;
            }
            #pragma unroll
            for (int mi = 0; mi < 4; mi++)
                #pragma unroll
                for (int nj = 0; nj < 4; nj++) {
                    mma16816(acc[mi][nj], ah[mi], bh[nj][0], bh[nj][1]);
                    mma16816(acc[mi][nj], ah[mi], bl[nj][0], bl[nj][1]);
                    mma16816(acc[mi][nj], al[mi], bh[nj][0], bh[nj][1]);
                }
        }
        __syncthreads();
    }

    // fused epilogue. dc is even -> (col, col+1) is a RoPE complex pair.
    const int dr = lane >> 2, dc = (lane & 3) * 2;
    #pragma unroll
    for (int mi = 0; mi < 4; mi++) {
        const int rowb = m0 + wm * 64 + mi * 16 + dr;
        #pragma unroll
        for (int nj = 0; nj < 4; nj++) {
            const int col = n0 + wn * 32 + nj * 8 + dc;
            #pragma unroll
            for (int rr = 0; rr < 2; rr++) {
                const int r = rowb + rr * 8;
                float e0 = acc[mi][nj][rr * 2], e1 = acc[mi][nj][rr * 2 + 1];
                if (MODE == 0) {
                    *(float2*)(C + (size_t)r * N + col) = make_float2(e0, e1);
                } else {
                    if (MODE == 1) {
                        int s  = r & (SEQ - 1);
                        int p  = (col & (HDIM - 1)) >> 1;
                        float cc = cosT[s * 64 + p], sn = sinT[s * 64 + p];
                        float o0 = e0 * cc - e1 * sn;
                        float o1 = e0 * sn + e1 * cc;
                        e0 = o0; e1 = o1;
                    }
                    float h0, l0f, h1, l1f;
                    split1(e0, h0, l0f); split1(e1, h1, l1f);
                    *(__nv_bfloat162*)(Ohi + (size_t)r * N + col) =
                        __nv_bfloat162(__float2bfloat16(h0),  __float2bfloat16(h1));
                    *(__nv_bfloat162*)(Olo + (size_t)r * N + col) =
                        __nv_bfloat162(__float2bfloat16(l0f), __float2bfloat16(l1f));
                }
            }
        }
    }
}

// ---------------- tensor-core flash attention (causal, MQA, bf16x3) ----------------
// CTA: 64 q rows, 4 warps x 16 rows, 128 threads, 2 CTAs/SM.
// KV tile 64 rows, SINGLE buffer (co-resident CTA hides load latency).
// Epilogue writes hi/lo bf16 directly (input of O-projection).
#define QP    136
#define QPB   (QP * 2)             // 272 bytes/row
#define ATT_SQH 0
#define ATT_SQL (64 * QPB)         // 17408
#define ATT_KV0 (2 * 64 * QPB)     // 34816
#define KVT   (64 * QPB)           // 17408
#define ATT_SMEM (ATT_KV0 + 4 * KVT)   // 104448 (~102 KB) -> 2 CTAs/SM

__global__ __launch_bounds__(128, 2) void attn_mma(
    const __nv_bfloat16* __restrict__ Qh, const __nv_bfloat16* __restrict__ Ql,
    const __nv_bfloat16* __restrict__ Kh, const __nv_bfloat16* __restrict__ Kl,
    const __nv_bfloat16* __restrict__ Vh, const __nv_bfloat16* __restrict__ Vl,
    __nv_bfloat16* __restrict__ Ahi, __nv_bfloat16* __restrict__ Alo) {
    const uint32_t sb = smem_to_u32(dyn_smem);
    const int t = threadIdx.x, w = t >> 5, lane = t & 31;
    const int b = blockIdx.z, h = blockIdx.y;
    const int qt = gridDim.x - 1 - blockIdx.x;      // big tiles first (tail shrink)
    const int q0 = qt * 64;
    const int nt = qt + 1;                          // causal KV tiles
    const float scale = 0.08838834764831845f;

    const int a_row = lane & 15, a_c8 = lane >> 4;
    const int kb_row = (lane & 7) + ((lane >> 4) << 3);
    const int kb_c8 = (lane >> 3) & 1;
    const int v_row = (lane & 7) + (((lane >> 3) & 1) << 3);
    const int v_c8 = lane >> 4;
    const int dr = lane >> 2, dc = (lane & 3) * 2;

    // ---- load Q tile (hi+lo): 64 rows x 16 chunks = 1024 chunks per half ----
    {
        const __nv_bfloat16* qsrc[2] = { Qh, Ql };
        #pragma unroll
        for (int half = 0; half < 2; half++) {
            uint32_t dst = sb + (half ? ATT_SQL : ATT_SQH);
            const __nv_bfloat16* s = qsrc[half] + ((size_t)(b * SEQ + q0)) * DMODEL + h * HDIM;
            #pragma unroll
            for (int it = 0; it < 8; it++) {
                int idx = t + it * 128;
                int row = idx >> 4, c = idx & 15;
                CP_ASYNC16(dst + (uint32_t)(row * QPB + c * 16), s + (size_t)row * DMODEL + c * 8);
            }
        }
    }
    auto load_kv = [&](int tile) {
        const size_t base = (size_t)(b * SEQ + tile * 64) * HDIM;
        const __nv_bfloat16* srcs[4] = { Kh + base, Kl + base, Vh + base, Vl + base };
        uint32_t bb = sb + ATT_KV0;
        #pragma unroll
        for (int part = 0; part < 4; part++) {
            #pragma unroll
            for (int it = 0; it < 8; it++) {
                int idx = t + it * 128;
                int row = idx >> 4, c = idx & 15;
                CP_ASYNC16(bb + (uint32_t)(part * KVT + row * QPB + c * 16),
                           srcs[part] + (size_t)row * HDIM + c * 8);
            }
        }
    };
    load_kv(0);
    CP_COMMIT();

    float o[16][4];
    #pragma unroll
    for (int nj = 0; nj < 16; nj++)
        #pragma unroll
        for (int e = 0; e < 4; e++) o[nj][e] = 0.f;
    float m0 = -1e30f, m1 = -1e30f, l0 = 0.f, l1 = 0.f;
    const int row0 = q0 + w * 16 + dr, row1 = row0 + 8;

    const uint32_t bQh = sb + ATT_SQH, bQl = sb + ATT_SQL;
    const uint32_t bKh = sb + ATT_KV0, bKl = bKh + KVT, bVh = bKh + 2 * KVT, bVl = bKh + 3 * KVT;

    for (int tt = 0; tt < nt; tt++) {
        CP_WAIT(0);
        __syncthreads();
        const int kv0 = tt * 64;

        // ---- S = Q K^T (bf16x3) ----
        float s[8][4];
        #pragma unroll
        for (int nj = 0; nj < 8; nj++)
            #pragma unroll
            for (int e = 0; e < 4; e++) s[nj][e] = 0.f;

        #pragma unroll
        for (int k = 0; k < 8; k++) {
            uint32_t qoff = (uint32_t)((w * 16 + a_row) * QPB + (k * 16 + a_c8 * 8) * 2);
            uint32_t ah[4], al[4];
            ldsm_x4(ah[0], ah[1], ah[2], ah[3], bQh + qoff);
            ldsm_x4(al[0], al[1], al[2], al[3], bQl + qoff);
            #pragma unroll
            for (int np = 0; np < 4; np++) {
                uint32_t koff = (uint32_t)((np * 16 + kb_row) * QPB + (k * 16 + kb_c8 * 8) * 2);
                uint32_t h0, h1, h2, h3, lo0, lo1, lo2, lo3;
                ldsm_x4(h0, h1, h2, h3, bKh + koff);
                ldsm_x4(lo0, lo1, lo2, lo3, bKl + koff);
                mma16816(s[2*np],     ah, h0, h1);
                mma16816(s[2*np],     ah, lo0, lo1);
                mma16816(s[2*np],     al, h0, h1);
                mma16816(s[2*np + 1], ah, h2, h3);
                mma16816(s[2*np + 1], ah, lo2, lo3);
                mma16816(s[2*np + 1], al, h2, h3);
            }
        }

        // ---- scale + causal mask ----
        const bool domask = (kv0 + 63 > q0);
        #pragma unroll
        for (int nj = 0; nj < 8; nj++) {
            #pragma unroll
            for (int e = 0; e < 4; e++) s[nj][e] *= scale;
            if (domask) {
                int cg = kv0 + nj * 8 + dc;
                if (cg     > row0) s[nj][0] = -1e30f;
                if (cg + 1 > row0) s[nj][1] = -1e30f;
                if (cg     > row1) s[nj][2] = -1e30f;
                if (cg + 1 > row1) s[nj][3] = -1e30f;
            }
        }

        // ---- online softmax ----
        float mx0 = -1e30f, mx1 = -1e30f;
        #pragma unroll
        for (int nj = 0; nj < 8; nj++) {
            mx0 = fmaxf(mx0, fmaxf(s[nj][0], s[nj][1]));
            mx1 = fmaxf(mx1, fmaxf(s[nj][2], s[nj][3]));
        }
        mx0 = fmaxf(mx0, __shfl_xor_sync(0xffffffffu, mx0, 1));
        mx0 = fmaxf(mx0, __shfl_xor_sync(0xffffffffu, mx0, 2));
        mx1 = fmaxf(mx1, __shfl_xor_sync(0xffffffffu, mx1, 1));
        mx1 = fmaxf(mx1, __shfl_xor_sync(0xffffffffu, mx1, 2));
        float mn0 = fmaxf(m0, mx0), mn1 = fmaxf(m1, mx1);
        float c0 = __expf(m0 - mn0), c1 = __expf(m1 - mn1);
        float sum0 = 0.f, sum1 = 0.f;
        #pragma unroll
        for (int nj = 0; nj < 8; nj++) {
            s[nj][0] = __expf(s[nj][0] - mn0); sum0 += s[nj][0];
            s[nj][1] = __expf(s[nj][1] - mn0); sum0 += s[nj][1];
            s[nj][2] = __expf(s[nj][2] - mn1); sum1 += s[nj][2];
            s[nj][3] = __expf(s[nj][3] - mn1); sum1 += s[nj][3];
        }
        sum0 += __shfl_xor_sync(0xffffffffu, sum0, 1);
        sum0 += __shfl_xor_sync(0xffffffffu, sum0, 2);
        sum1 += __shfl_xor_sync(0xffffffffu, sum1, 1);
        sum1 += __shfl_xor_sync(0xffffffffu, sum1, 2);
        l0 = l0 * c0 + sum0; l1 = l1 * c1 + sum1;
        m0 = mn0; m1 = mn1;
        #pragma unroll
        for (int nj = 0; nj < 16; nj++) {
            o[nj][0] *= c0; o[nj][1] *= c0;
            o[nj][2] *= c1; o[nj][3] *= c1;
        }

        // ---- O += P V (bf16x3; P split in registers) ----
        #pragma unroll
        for (int kq = 0; kq < 4; kq++) {
            float ph[8], pl[8];
            #pragma unroll
            for (int e = 0; e < 4; e++) {
                float p0 = s[2*kq][e], p1 = s[2*kq + 1][e];
                split1(p0, ph[e], pl[e]);
                split1(p1, ph[4 + e], pl[4 + e]);
            }
            uint32_t pah[4], pal[4];
            pah[0] = pack_bf16(ph[0], ph[1]); pah[1] = pack_bf16(ph[2], ph[3]);
            pah[2] = pack_bf16(ph[4], ph[5]); pah[3] = pack_bf16(ph[6], ph[7]);
            pal[0] = pack_bf16(pl[0], pl[1]); pal[1] = pack_bf16(pl[2], pl[3]);
            pal[2] = pack_bf16(pl[4], pl[5]); pal[3] = pack_bf16(pl[6], pl[7]);

            #pragma unroll
            for (int np = 0; np < 8; np++) {
                uint32_t voff = (uint32_t)((kq * 16 + v_row) * QPB + (np * 16 + v_c8 * 8) * 2);
                uint32_t h0, h1, h2, h3, lo0, lo1, lo2, lo3;
                ldsm_x4t(h0, h1, h2, h3, bVh + voff);
                ldsm_x4t(lo0, lo1, lo2, lo3, bVl + voff);
                mma16816(o[2*np],     pah, h0, h1);
                mma16816(o[2*np],     pah, lo0, lo1);
                mma16816(o[2*np],     pal, h0, h1);
                mma16816(o[2*np + 1], pah, h2, h3);
                mma16816(o[2*np + 1], pah, lo2, lo3);
                mma16816(o[2*np + 1], pal, h2, h3);
            }
        }
        __syncthreads();                   // reads done before refilling single buffer
        if (tt + 1 < nt) { load_kv(tt + 1); CP_COMMIT(); }
    }

    // ---- epilogue: normalize + hi/lo split, write bf16 [B,S,D] ----
    const float inv0 = 1.f / l0, inv1 = 1.f / l1;
    const size_t ob0 = (size_t)(b * SEQ + row0) * DMODEL + h * HDIM;
    const size_t ob1 = (size_t)(b * SEQ + row1) * DMODEL + h * HDIM;
    #pragma unroll
    for (int nj = 0; nj < 16; nj++) {
        float v00 = o[nj][0] * inv0, v01 = o[nj][1] * inv0;
        float v10 = o[nj][2] * inv1, v11 = o[nj][3] * inv1;
        float h0, l0f, h1, l1f;
        split1(v00, h0, l0f); split1(v01, h1, l1f);
        *(__nv_bfloat162*)(Ahi + ob0 + nj * 8 + dc) =
            __nv_bfloat162(__float2bfloat16(h0),  __float2bfloat16(h1));
        *(__nv_bfloat162*)(Alo + ob0 + nj * 8 + dc) =
            __nv_bfloat162(__float2bfloat16(l0f), __float2bfloat16(l1f));
        split1(v10, h0, l0f); split1(v11, h1, l1f);
        *(__nv_bfloat162*)(Ahi + ob1 + nj * 8 + dc) =
            __nv_bfloat162(__float2bfloat16(h0),  __float2bfloat16(h1));
        *(__nv_bfloat162*)(Alo + ob1 + nj * 8 + dc) =
            __nv_bfloat162(__float2bfloat16(l0f), __float2bfloat16(l1f));
    }
}

// ---------------- launch ----------------
extern "C" void kernel_launch(void* const* d_in, const int* in_sizes, int n_in,
                              void* d_out, int out_size) {
    const float* x  = (const float*)d_in[0];
    const float* Wq = (const float*)d_in[1];
    const float* Wk = (const float*)d_in[2];
    const float* Wv = (const float*)d_in[3];
    const float* Wo = (const float*)d_in[4];
    const float* rc = (const float*)d_in[5];
    const float* rs = (const float*)d_in[6];
    float* out = (float*)d_out;

    __nv_bfloat16 *xh, *xl, *ah, *al, *wqh, *wql, *woh, *wol, *wkh, *wkl, *wvh, *wvl;
    __nv_bfloat16 *qbh, *qbl, *kbh, *kbl, *vbh, *vbl;
    cudaGetSymbolAddress((void**)&xh,  g_xh);  cudaGetSymbolAddress((void**)&xl,  g_xl);
    cudaGetSymbolAddress((void**)&ah,  g_ah);  cudaGetSymbolAddress((void**)&al,  g_al);
    cudaGetSymbolAddress((void**)&wqh, g_wqh); cudaGetSymbolAddress((void**)&wql, g_wql);
    cudaGetSymbolAddress((void**)&woh, g_woh); cudaGetSymbolAddress((void**)&wol, g_wol);
    cudaGetSymbolAddress((void**)&wkh, g_wkh); cudaGetSymbolAddress((void**)&wkl, g_wkl);
    cudaGetSymbolAddress((void**)&wvh, g_wvh); cudaGetSymbolAddress((void**)&wvl, g_wvl);
    cudaGetSymbolAddress((void**)&qbh, g_qbh); cudaGetSymbolAddress((void**)&qbl, g_qbl);
    cudaGetSymbolAddress((void**)&kbh, g_kbh); cudaGetSymbolAddress((void**)&kbl, g_kbl);
    cudaGetSymbolAddress((void**)&vbh, g_vbh); cudaGetSymbolAddress((void**)&vbl, g_vbl);

    const int M = MROWS;
    const int gemmSmem = 2 * BUF_B;
    cudaFuncSetAttribute(gemm_mma<0>, cudaFuncAttributeMaxDynamicSharedMemorySize, gemmSmem);
    cudaFuncSetAttribute(gemm_mma<1>, cudaFuncAttributeMaxDynamicSharedMemorySize, gemmSmem);
    cudaFuncSetAttribute(gemm_mma<2>, cudaFuncAttributeMaxDynamicSharedMemorySize, gemmSmem);
    cudaFuncSetAttribute(attn_mma, cudaFuncAttributeMaxDynamicSharedMemorySize, ATT_SMEM);

    // split fp32 inputs/weights -> bf16 hi/lo
    { int n = M * DMODEL;      split_bf16<<<(n + 255) / 256, 256>>>(x,  xh,  xl,  n); }
    { int n = DMODEL * DMODEL; split_bf16<<<(n + 255) / 256, 256>>>(Wq, wqh, wql, n); }
    { int n = HDIM * DMODEL;   split_bf16<<<(n + 255) / 256, 256>>>(Wk, wkh, wkl, n); }
    { int n = HDIM * DMODEL;   split_bf16<<<(n + 255) / 256, 256>>>(Wv, wvh, wvl, n); }
    { int n = DMODEL * DMODEL; split_bf16<<<(n + 255) / 256, 256>>>(Wo, woh, wol, n); }

    // projections with fused epilogues: Q,K get RoPE+split; V gets split
    gemm_mma<1><<<dim3(DMODEL / 128, M / 128), 256, gemmSmem>>>(
        xh, xl, wqh, wql, nullptr, qbh, qbl, rc, rs, DMODEL, DMODEL);
    gemm_mma<1><<<dim3(HDIM / 128, M / 128), 256, gemmSmem>>>(
        xh, xl, wkh, wkl, nullptr, kbh, kbl, rc, rs, HDIM, DMODEL);
    gemm_mma<2><<<dim3(HDIM / 128, M / 128), 256, gemmSmem>>>(
        xh, xl, wvh, wvl, nullptr, vbh, vbl, nullptr, nullptr, HDIM, DMODEL);

    // tensor-core flash attention -> hi/lo bf16 directly
    attn_mma<<<dim3(SEQ / 64, NHEAD, BATCH), 128, ATT_SMEM>>>(
        qbh, qbl, kbh, kbl, vbh, vbl, ah, al);

    // output projection -> fp32 out
    gemm_mma<0><<<dim3(DMODEL / 128, M / 128), 256, gemmSmem>>>(
        ah, al, woh, wol, out, nullptr, nullptr, nullptr, nullptr, DMODEL, DMODEL);
}

// round 10
// speedup vs baseline: 3.4304x; 1.0662x over previous
#include <cuda_runtime.h>
#include <cuda_bf16.h>
#include <cstdint>

#define SEQ    2048
#define DMODEL 2048
#define NHEAD  16
#define HDIM   128
#define BATCH  2
#define MROWS  (BATCH * SEQ)   // 4096

extern __shared__ char dyn_smem[];

// ---------------- scratch (no allocations allowed) ----------------
__device__ __nv_bfloat16 g_xh[MROWS * DMODEL],  g_xl[MROWS * DMODEL];
__device__ __nv_bfloat16 g_ah[MROWS * DMODEL],  g_al[MROWS * DMODEL];
__device__ __nv_bfloat16 g_wqh[DMODEL * DMODEL], g_wql[DMODEL * DMODEL];
__device__ __nv_bfloat16 g_woh[DMODEL * DMODEL], g_wol[DMODEL * DMODEL];
__device__ __nv_bfloat16 g_wkh[HDIM * DMODEL],   g_wkl[HDIM * DMODEL];
__device__ __nv_bfloat16 g_wvh[HDIM * DMODEL],   g_wvl[HDIM * DMODEL];
__device__ __nv_bfloat16 g_qbh[MROWS * DMODEL], g_qbl[MROWS * DMODEL];
__device__ __nv_bfloat16 g_kbh[MROWS * HDIM],   g_kbl[MROWS * HDIM];
__device__ __nv_bfloat16 g_vbh[MROWS * HDIM],   g_vbl[MROWS * HDIM];

// ---------------- helpers ----------------
__device__ __forceinline__ uint32_t smem_to_u32(const void* p) {
    uint32_t a;
    asm("{ .reg .u64 t; cvta.to.shared.u64 t, %1; cvt.u32.u64 %0, t; }" : "=r"(a) : "l"(p));
    return a;
}

#define CP_ASYNC16(saddr, gptr) \
    asm volatile("cp.async.cg.shared.global [%0], [%1], 16;" :: "r"(saddr), "l"(gptr))
#define CP_COMMIT() asm volatile("cp.async.commit_group;" ::: "memory")
#define CP_WAIT(n)  asm volatile("cp.async.wait_group %0;" :: "n"(n) : "memory")

__device__ __forceinline__ void ldsm_x4(uint32_t& r0, uint32_t& r1, uint32_t& r2, uint32_t& r3,
                                        uint32_t addr) {
    asm volatile("ldmatrix.sync.aligned.m8n8.x4.shared.b16 {%0,%1,%2,%3}, [%4];"
                 : "=r"(r0), "=r"(r1), "=r"(r2), "=r"(r3) : "r"(addr));
}
__device__ __forceinline__ void ldsm_x4t(uint32_t& r0, uint32_t& r1, uint32_t& r2, uint32_t& r3,
                                         uint32_t addr) {
    asm volatile("ldmatrix.sync.aligned.m8n8.x4.trans.shared.b16 {%0,%1,%2,%3}, [%4];"
                 : "=r"(r0), "=r"(r1), "=r"(r2), "=r"(r3) : "r"(addr));
}
__device__ __forceinline__ void mma16816(float* d, const uint32_t* a, uint32_t b0, uint32_t b1) {
    asm volatile(
        "mma.sync.aligned.m16n8k16.row.col.f32.bf16.bf16.f32 "
        "{%0,%1,%2,%3}, {%4,%5,%6,%7}, {%8,%9}, {%0,%1,%2,%3};"
        : "+f"(d[0]), "+f"(d[1]), "+f"(d[2]), "+f"(d[3])
        : "r"(a[0]), "r"(a[1]), "r"(a[2]), "r"(a[3]), "r"(b0), "r"(b1));
}
__device__ __forceinline__ uint32_t pack_bf16(float lo, float hi) {
    uint32_t r;
    asm("cvt.rn.bf16x2.f32 %0, %1, %2;" : "=r"(r) : "f"(hi), "f"(lo));
    return r;
}
__device__ __forceinline__ void split1(float v, float& h, float& l) {
    __nv_bfloat16 hb = __float2bfloat16(v);
    h = __bfloat162float(hb);
    l = v - h;
}

// ---------------- fp32 -> bf16 hi/lo split ----------------
__global__ void split_bf16(const float* __restrict__ src,
                           __nv_bfloat16* __restrict__ hi,
                           __nv_bfloat16* __restrict__ lo, int n) {
    int i = blockIdx.x * blockDim.x + threadIdx.x;
    if (i >= n) return;
    float v = src[i];
    __nv_bfloat16 h = __float2bfloat16(v);
    hi[i] = h;
    lo[i] = __float2bfloat16(v - __bfloat162float(h));
}

// ---------------- mma.sync bf16x3 GEMM with fused epilogues (validated) ----------------
#define TPITCH 40
#define TILE_B (128 * TPITCH * 2)
#define BUF_B  (4 * TILE_B)

template <int MODE>
__global__ __launch_bounds__(256) void gemm_mma(const __nv_bfloat16* __restrict__ Ah,
                                                const __nv_bfloat16* __restrict__ Al,
                                                const __nv_bfloat16* __restrict__ Bh,
                                                const __nv_bfloat16* __restrict__ Bl,
                                                float* __restrict__ C,
                                                __nv_bfloat16* __restrict__ Ohi,
                                                __nv_bfloat16* __restrict__ Olo,
                                                const float* __restrict__ cosT,
                                                const float* __restrict__ sinT,
                                                int N, int K) {
    const uint32_t sbase = smem_to_u32(dyn_smem);
    const int t = threadIdx.x, wid = t >> 5, lane = t & 31;
    const int m0 = blockIdx.y * 128, n0 = blockIdx.x * 128;
    const int wm = wid & 1, wn = wid >> 1;

    const __nv_bfloat16* srcs[4] = { Ah + (size_t)m0 * K, Al + (size_t)m0 * K,
                                     Bh + (size_t)n0 * K, Bl + (size_t)n0 * K };
    const int r0c = (t + 0)   >> 2, s0c = (t + 0)   & 3;
    const int r1c = (t + 256) >> 2, s1c = (t + 256) & 3;

    float acc[4][4][4];
    #pragma unroll
    for (int i = 0; i < 4; i++)
        #pragma unroll
        for (int j = 0; j < 4; j++)
            #pragma unroll
            for (int e = 0; e < 4; e++) acc[i][j][e] = 0.f;

    const int NC = K / 32;
    const int a_row = lane & 15, a_c8 = lane >> 4;
    const int b_row = (lane & 7) + ((lane >> 4) << 3), b_c8 = (lane >> 3) & 1;

    auto load_chunk = [&](int c, int buf) {
        const int k0 = c * 32;
        uint32_t sb = sbase + buf * BUF_B;
        #pragma unroll
        for (int tile = 0; tile < 4; tile++) {
            const __nv_bfloat16* s = srcs[tile] + k0;
            uint32_t td = sb + tile * TILE_B;
            CP_ASYNC16(td + (uint32_t)(r0c * TPITCH + s0c * 8) * 2, s + (size_t)r0c * K + s0c * 8);
            CP_ASYNC16(td + (uint32_t)(r1c * TPITCH + s1c * 8) * 2, s + (size_t)r1c * K + s1c * 8);
        }
    };

    load_chunk(0, 0);
    CP_COMMIT();

    for (int c = 0; c < NC; c++) {
        if (c + 1 < NC) { load_chunk(c + 1, (c + 1) & 1); CP_COMMIT(); CP_WAIT(1); }
        else            { CP_WAIT(0); }
        __syncthreads();

        const uint32_t sb  = sbase + (c & 1) * BUF_B;
        const uint32_t sAh = sb, sAl = sb + TILE_B, sBh = sb + 2 * TILE_B, sBl = sb + 3 * TILE_B;

        #pragma unroll
        for (int s = 0; s < 2; s++) {
            const int kc = s * 16;
            uint32_t ah[4][4], al[4][4], bh[4][2], bl[4][2];
            #pragma unroll
            for (int mi = 0; mi < 4; mi++) {
                uint32_t off = (uint32_t)((wm * 64 + mi * 16 + a_row) * TPITCH + kc + a_c8 * 8) * 2;
                ldsm_x4(ah[mi][0], ah[mi][1], ah[mi][2], ah[mi][3], sAh + off);
                ldsm_x4(al[mi][0], al[mi][1], al[mi][2], al[mi][3], sAl + off);
            }
            #pragma unroll
            for (int np = 0; np < 2; np++) {
                uint32_t off = (uint32_t)((wn * 32 + np * 16 + b_row) * TPITCH + kc + b_c8 * 8) * 2;
                uint32_t h0, h1, h2, h3, l0, l1, l2, l3;
                ldsm_x4(h0, h1, h2, h3, sBh + off);
                ldsm_x4(l0, l1, l2, l3, sBl + off);
                bh[np*2][0] = h0; bh[np*2][1] = h1; bh[np*2+1][0] = h2; bh[np*2+1][1] = h3;
                bl[np*2][0] = l0; bl[np*2][1] = l1; bl[np*2+1][0] = l2; bl[np*2+1][1] = l3;
            }
            #pragma unroll
            for (int mi = 0; mi < 4; mi++)
                #pragma unroll
                for (int nj = 0; nj < 4; nj++) {
                    mma16816(acc[mi][nj], ah[mi], bh[nj][0], bh[nj][1]);
                    mma16816(acc[mi][nj], ah[mi], bl[nj][0], bl[nj][1]);
                    mma16816(acc[mi][nj], al[mi], bh[nj][0], bh[nj][1]);
                }
        }
        __syncthreads();
    }

    const int dr = lane >> 2, dc = (lane & 3) * 2;
    #pragma unroll
    for (int mi = 0; mi < 4; mi++) {
        const int rowb = m0 + wm * 64 + mi * 16 + dr;
        #pragma unroll
        for (int nj = 0; nj < 4; nj++) {
            const int col = n0 + wn * 32 + nj * 8 + dc;
            #pragma unroll
            for (int rr = 0; rr < 2; rr++) {
                const int r = rowb + rr * 8;
                float e0 = acc[mi][nj][rr * 2], e1 = acc[mi][nj][rr * 2 + 1];
                if (MODE == 0) {
                    *(float2*)(C + (size_t)r * N + col) = make_float2(e0, e1);
                } else {
                    if (MODE == 1) {
                        int s  = r & (SEQ - 1);
                        int p  = (col & (HDIM - 1)) >> 1;
                        float cc = cosT[s * 64 + p], sn = sinT[s * 64 + p];
                        float o0 = e0 * cc - e1 * sn;
                        float o1 = e0 * sn + e1 * cc;
                        e0 = o0; e1 = o1;
                    }
                    float h0, l0f, h1, l1f;
                    split1(e0, h0, l0f); split1(e1, h1, l1f);
                    *(__nv_bfloat162*)(Ohi + (size_t)r * N + col) =
                        __nv_bfloat162(__float2bfloat16(h0),  __float2bfloat16(h1));
                    *(__nv_bfloat162*)(Olo + (size_t)r * N + col) =
                        __nv_bfloat162(__float2bfloat16(l0f), __float2bfloat16(l1f));
                }
            }
        }
    }
}

// ---------------- tensor-core flash attention (MQA heads folded into M) ----------------
// CTA: M = 128 rows = 8 heads x 16 q-rows. 256 thr, 8 warps: warp w <-> head hg*8+w.
// KV tile 64 rows, DOUBLE buffered (all heads share KV -> 8x L2 amortization).
#define QP    136
#define QPB   (QP * 2)               // 272 bytes/row
#define ATT_SQH 0
#define ATT_SQL (128 * QPB)          // 34816
#define ATT_KV0 (2 * 128 * QPB)      // 69632
#define KVT   (64 * QPB)             // 17408
#define KVBUF (4 * KVT)              // 69632 : Kh, Kl, Vh, Vl
#define ATT_SMEM (ATT_KV0 + 2 * KVBUF)   // 208896

__global__ __launch_bounds__(256, 1) void attn_mma(
    const __nv_bfloat16* __restrict__ Qh, const __nv_bfloat16* __restrict__ Ql,
    const __nv_bfloat16* __restrict__ Kh, const __nv_bfloat16* __restrict__ Kl,
    const __nv_bfloat16* __restrict__ Vh, const __nv_bfloat16* __restrict__ Vl,
    __nv_bfloat16* __restrict__ Ahi, __nv_bfloat16* __restrict__ Alo) {
    const uint32_t sb = smem_to_u32(dyn_smem);
    const int t = threadIdx.x, w = t >> 5, lane = t & 31;
    const int b = blockIdx.z, hg = blockIdx.y;       // head group (8 heads)
    const int qt = gridDim.x - 1 - blockIdx.x;       // big tiles first
    const int q0 = qt * 16;                          // 16 q-rows per CTA
    const int nt = qt / 4 + 1;                       // causal KV tiles of 64
    const float scale = 0.08838834764831845f;

    const int a_row = lane & 15, a_c8 = lane >> 4;
    const int kb_row = (lane & 7) + ((lane >> 4) << 3);
    const int kb_c8 = (lane >> 3) & 1;
    const int v_row = (lane & 7) + (((lane >> 3) & 1) << 3);
    const int v_c8 = lane >> 4;
    const int dr = lane >> 2, dc = (lane & 3) * 2;

    // ---- load Q: smem row m (0..127) = head hg*8 + m/16, q-row q0 + (m&15) ----
    {
        const __nv_bfloat16* qsrc[2] = { Qh, Ql };
        #pragma unroll
        for (int half = 0; half < 2; half++) {
            uint32_t dst = sb + (half ? ATT_SQL : ATT_SQH);
            #pragma unroll
            for (int it = 0; it < 8; it++) {
                int idx = t + it * 256;              // 0..2047 = 128 rows x 16 chunks
                int m = idx >> 4, c = idx & 15;
                int head = hg * 8 + (m >> 4);
                const __nv_bfloat16* s = qsrc[half]
                    + ((size_t)(b * SEQ + q0 + (m & 15))) * DMODEL + head * HDIM + c * 8;
                CP_ASYNC16(dst + (uint32_t)(m * QPB + c * 16), s);
            }
        }
    }
    auto load_kv = [&](int tile, int buf) {
        const size_t base = (size_t)(b * SEQ + tile * 64) * HDIM;
        const __nv_bfloat16* srcs[4] = { Kh + base, Kl + base, Vh + base, Vl + base };
        uint32_t bb = sb + ATT_KV0 + buf * KVBUF;
        #pragma unroll
        for (int part = 0; part < 4; part++) {
            #pragma unroll
            for (int it = 0; it < 4; it++) {
                int idx = t + it * 256;              // 0..1023 = 64 rows x 16 chunks
                int row = idx >> 4, c = idx & 15;
                CP_ASYNC16(bb + (uint32_t)(part * KVT + row * QPB + c * 16),
                           srcs[part] + (size_t)row * HDIM + c * 8);
            }
        }
    };
    load_kv(0, 0);
    CP_COMMIT();

    float o[16][4];
    #pragma unroll
    for (int nj = 0; nj < 16; nj++)
        #pragma unroll
        for (int e = 0; e < 4; e++) o[nj][e] = 0.f;
    float m0 = -1e30f, m1 = -1e30f, l0 = 0.f, l1 = 0.f;
    const int row0 = q0 + dr, row1 = row0 + 8;       // same q-rows for every warp

    const uint32_t bQh = sb + ATT_SQH, bQl = sb + ATT_SQL;

    for (int tt = 0; tt < nt; tt++) {
        if (tt + 1 < nt) { load_kv(tt + 1, (tt + 1) & 1); CP_COMMIT(); CP_WAIT(1); }
        else             { CP_WAIT(0); }
        __syncthreads();

        const int kv0 = tt * 64;
        const uint32_t bKh = sb + ATT_KV0 + (tt & 1) * KVBUF;
        const uint32_t bKl = bKh + KVT, bVh = bKh + 2 * KVT, bVl = bKh + 3 * KVT;

        // ---- S = Q K^T (bf16x3) ----
        float s[8][4];
        #pragma unroll
        for (int nj = 0; nj < 8; nj++)
            #pragma unroll
            for (int e = 0; e < 4; e++) s[nj][e] = 0.f;

        #pragma unroll
        for (int k = 0; k < 8; k++) {
            uint32_t qoff = (uint32_t)((w * 16 + a_row) * QPB + (k * 16 + a_c8 * 8) * 2);
            uint32_t ah[4], al[4];
            ldsm_x4(ah[0], ah[1], ah[2], ah[3], bQh + qoff);
            ldsm_x4(al[0], al[1], al[2], al[3], bQl + qoff);
            #pragma unroll
            for (int np = 0; np < 4; np++) {
                uint32_t koff = (uint32_t)((np * 16 + kb_row) * QPB + (k * 16 + kb_c8 * 8) * 2);
                uint32_t h0, h1, h2, h3, lo0, lo1, lo2, lo3;
                ldsm_x4(h0, h1, h2, h3, bKh + koff);
                ldsm_x4(lo0, lo1, lo2, lo3, bKl + koff);
                mma16816(s[2*np],     ah, h0, h1);
                mma16816(s[2*np],     ah, lo0, lo1);
                mma16816(s[2*np],     al, h0, h1);
                mma16816(s[2*np + 1], ah, h2, h3);
                mma16816(s[2*np + 1], ah, lo2, lo3);
                mma16816(s[2*np + 1], al, h2, h3);
            }
        }

        // ---- scale + causal mask (row0/row1 identical across warps) ----
        const bool domask = (kv0 + 63 > q0);
        #pragma unroll
        for (int nj = 0; nj < 8; nj++) {
            #pragma unroll
            for (int e = 0; e < 4; e++) s[nj][e] *= scale;
            if (domask) {
                int cg = kv0 + nj * 8 + dc;
                if (cg     > row0) s[nj][0] = -1e30f;
                if (cg + 1 > row0) s[nj][1] = -1e30f;
                if (cg     > row1) s[nj][2] = -1e30f;
                if (cg + 1 > row1) s[nj][3] = -1e30f;
            }
        }

        // ---- online softmax ----
        float mx0 = -1e30f, mx1 = -1e30f;
        #pragma unroll
        for (int nj = 0; nj < 8; nj++) {
            mx0 = fmaxf(mx0, fmaxf(s[nj][0], s[nj][1]));
            mx1 = fmaxf(mx1, fmaxf(s[nj][2], s[nj][3]));
        }
        mx0 = fmaxf(mx0, __shfl_xor_sync(0xffffffffu, mx0, 1));
        mx0 = fmaxf(mx0, __shfl_xor_sync(0xffffffffu, mx0, 2));
        mx1 = fmaxf(mx1, __shfl_xor_sync(0xffffffffu, mx1, 1));
        mx1 = fmaxf(mx1, __shfl_xor_sync(0xffffffffu, mx1, 2));
        float mn0 = fmaxf(m0, mx0), mn1 = fmaxf(m1, mx1);
        float c0 = __expf(m0 - mn0), c1 = __expf(m1 - mn1);
        float sum0 = 0.f, sum1 = 0.f;
        #pragma unroll
        for (int nj = 0; nj < 8; nj++) {
            s[nj][0] = __expf(s[nj][0] - mn0); sum0 += s[nj][0];
            s[nj][1] = __expf(s[nj][1] - mn0); sum0 += s[nj][1];
            s[nj][2] = __expf(s[nj][2] - mn1); sum1 += s[nj][2];
            s[nj][3] = __expf(s[nj][3] - mn1); sum1 += s[nj][3];
        }
        sum0 += __shfl_xor_sync(0xffffffffu, sum0, 1);
        sum0 += __shfl_xor_sync(0xffffffffu, sum0, 2);
        sum1 += __shfl_xor_sync(0xffffffffu, sum1, 1);
        sum1 += __shfl_xor_sync(0xffffffffu, sum1, 2);
        l0 = l0 * c0 + sum0; l1 = l1 * c1 + sum1;
        m0 = mn0; m1 = mn1;
        #pragma unroll
        for (int nj = 0; nj < 16; nj++) {
            o[nj][0] *= c0; o[nj][1] *= c0;
            o[nj][2] *= c1; o[nj][3] *= c1;
        }

        // ---- O += P V (bf16x3; P split in registers) ----
        #pragma unroll
        for (int kq = 0; kq < 4; kq++) {
            float ph[8], pl[8];
            #pragma unroll
            for (int e = 0; e < 4; e++) {
                float p0 = s[2*kq][e], p1 = s[2*kq + 1][e];
                split1(p0, ph[e], pl[e]);
                split1(p1, ph[4 + e], pl[4 + e]);
            }
            uint32_t pah[4], pal[4];
            pah[0] = pack_bf16(ph[0], ph[1]); pah[1] = pack_bf16(ph[2], ph[3]);
            pah[2] = pack_bf16(ph[4], ph[5]); pah[3] = pack_bf16(ph[6], ph[7]);
            pal[0] = pack_bf16(pl[0], pl[1]); pal[1] = pack_bf16(pl[2], pl[3]);
            pal[2] = pack_bf16(pl[4], pl[5]); pal[3] = pack_bf16(pl[6], pl[7]);

            #pragma unroll
            for (int np = 0; np < 8; np++) {
                uint32_t voff = (uint32_t)((kq * 16 + v_row) * QPB + (np * 16 + v_c8 * 8) * 2);
                uint32_t h0, h1, h2, h3, lo0, lo1, lo2, lo3;
                ldsm_x4t(h0, h1, h2, h3, bVh + voff);
                ldsm_x4t(lo0, lo1, lo2, lo3, bVl + voff);
                mma16816(o[2*np],     pah, h0, h1);
                mma16816(o[2*np],     pah, lo0, lo1);
                mma16816(o[2*np],     pal, h0, h1);
                mma16816(o[2*np + 1], pah, h2, h3);
                mma16816(o[2*np + 1], pah, lo2, lo3);
                mma16816(o[2*np + 1], pal, h2, h3);
            }
        }
        __syncthreads();
    }

    // ---- epilogue: normalize + hi/lo split, warp w's head = hg*8+w ----
    const float inv0 = 1.f / l0, inv1 = 1.f / l1;
    const int head = hg * 8 + w;
    const size_t ob0 = (size_t)(b * SEQ + row0) * DMODEL + head * HDIM;
    const size_t ob1 = (size_t)(b * SEQ + row1) * DMODEL + head * HDIM;
    #pragma unroll
    for (int nj = 0; nj < 16; nj++) {
        float v00 = o[nj][0] * inv0, v01 = o[nj][1] * inv0;
        float v10 = o[nj][2] * inv1, v11 = o[nj][3] * inv1;
        float h0, l0f, h1, l1f;
        split1(v00, h0, l0f); split1(v01, h1, l1f);
        *(__nv_bfloat162*)(Ahi + ob0 + nj * 8 + dc) =
            __nv_bfloat162(__float2bfloat16(h0),  __float2bfloat16(h1));
        *(__nv_bfloat162*)(Alo + ob0 + nj * 8 + dc) =
            __nv_bfloat162(__float2bfloat16(l0f), __float2bfloat16(l1f));
        split1(v10, h0, l0f); split1(v11, h1, l1f);
        *(__nv_bfloat162*)(Ahi + ob1 + nj * 8 + dc) =
            __nv_bfloat162(__float2bfloat16(h0),  __float2bfloat16(h1));
        *(__nv_bfloat162*)(Alo + ob1 + nj * 8 + dc) =
            __nv_bfloat162(__float2bfloat16(l0f), __float2bfloat16(l1f));
    }
}

// ---------------- launch ----------------
extern "C" void kernel_launch(void* const* d_in, const int* in_sizes, int n_in,
                              void* d_out, int out_size) {
    const float* x  = (const float*)d_in[0];
    const float* Wq = (const float*)d_in[1];
    const float* Wk = (const float*)d_in[2];
    const float* Wv = (const float*)d_in[3];
    const float* Wo = (const float*)d_in[4];
    const float* rc = (const float*)d_in[5];
    const float* rs = (const float*)d_in[6];
    float* out = (float*)d_out;

    __nv_bfloat16 *xh, *xl, *ah, *al, *wqh, *wql, *woh, *wol, *wkh, *wkl, *wvh, *wvl;
    __nv_bfloat16 *qbh, *qbl, *kbh, *kbl, *vbh, *vbl;
    cudaGetSymbolAddress((void**)&xh,  g_xh);  cudaGetSymbolAddress((void**)&xl,  g_xl);
    cudaGetSymbolAddress((void**)&ah,  g_ah);  cudaGetSymbolAddress((void**)&al,  g_al);
    cudaGetSymbolAddress((void**)&wqh, g_wqh); cudaGetSymbolAddress((void**)&wql, g_wql);
    cudaGetSymbolAddress((void**)&woh, g_woh); cudaGetSymbolAddress((void**)&wol, g_wol);
    cudaGetSymbolAddress((void**)&wkh, g_wkh); cudaGetSymbolAddress((void**)&wkl, g_wkl);
    cudaGetSymbolAddress((void**)&wvh, g_wvh); cudaGetSymbolAddress((void**)&wvl, g_wvl);
    cudaGetSymbolAddress((void**)&qbh, g_qbh); cudaGetSymbolAddress((void**)&qbl, g_qbl);
    cudaGetSymbolAddress((void**)&kbh, g_kbh); cudaGetSymbolAddress((void**)&kbl, g_kbl);
    cudaGetSymbolAddress((void**)&vbh, g_vbh); cudaGetSymbolAddress((void**)&vbl, g_vbl);

    const int M = MROWS;
    const int gemmSmem = 2 * BUF_B;
    cudaFuncSetAttribute(gemm_mma<0>, cudaFuncAttributeMaxDynamicSharedMemorySize, gemmSmem);
    cudaFuncSetAttribute(gemm_mma<1>, cudaFuncAttributeMaxDynamicSharedMemorySize, gemmSmem);
    cudaFuncSetAttribute(gemm_mma<2>, cudaFuncAttributeMaxDynamicSharedMemorySize, gemmSmem);
    cudaFuncSetAttribute(attn_mma, cudaFuncAttributeMaxDynamicSharedMemorySize, ATT_SMEM);

    // split fp32 inputs/weights -> bf16 hi/lo
    { int n = M * DMODEL;      split_bf16<<<(n + 255) / 256, 256>>>(x,  xh,  xl,  n); }
    { int n = DMODEL * DMODEL; split_bf16<<<(n + 255) / 256, 256>>>(Wq, wqh, wql, n); }
    { int n = HDIM * DMODEL;   split_bf16<<<(n + 255) / 256, 256>>>(Wk, wkh, wkl, n); }
    { int n = HDIM * DMODEL;   split_bf16<<<(n + 255) / 256, 256>>>(Wv, wvh, wvl, n); }
    { int n = DMODEL * DMODEL; split_bf16<<<(n + 255) / 256, 256>>>(Wo, woh, wol, n); }

    // projections with fused epilogues
    gemm_mma<1><<<dim3(DMODEL / 128, M / 128), 256, gemmSmem>>>(
        xh, xl, wqh, wql, nullptr, qbh, qbl, rc, rs, DMODEL, DMODEL);
    gemm_mma<1><<<dim3(HDIM / 128, M / 128), 256, gemmSmem>>>(
        xh, xl, wkh, wkl, nullptr, kbh, kbl, rc, rs, HDIM, DMODEL);
    gemm_mma<2><<<dim3(HDIM / 128, M / 128), 256, gemmSmem>>>(
        xh, xl, wvh, wvl, nullptr, vbh, vbl, nullptr, nullptr, HDIM, DMODEL);

    // flash attention: heads folded into M (8 heads/CTA), 16 q-rows/CTA
    attn_mma<<<dim3(SEQ / 16, NHEAD / 8, BATCH), 256, ATT_SMEM>>>(
        qbh, qbl, kbh, kbl, vbh, vbl, ah, al);

    // output projection -> fp32 out
    gemm_mma<0><<<dim3(DMODEL / 128, M / 128), 256, gemmSmem>>>(
        ah, al, woh, wol, out, nullptr, nullptr, nullptr, nullptr, DMODEL, DMODEL);
}

// round 13
// speedup vs baseline: 3.7254x; 1.0860x over previous
#include <cuda_runtime.h>
#include <cuda_bf16.h>
#include <cstdint>

#define SEQ    2048
#define DMODEL 2048
#define NHEAD  16
#define HDIM   128
#define BATCH  2
#define MROWS  (BATCH * SEQ)   // 4096

extern __shared__ char dyn_smem[];

// ---------------- scratch (no allocations allowed) ----------------
__device__ __nv_bfloat16 g_xh[MROWS * DMODEL],  g_xl[MROWS * DMODEL];
__device__ __nv_bfloat16 g_ah[MROWS * DMODEL],  g_al[MROWS * DMODEL];
__device__ __nv_bfloat16 g_wqh[DMODEL * DMODEL], g_wql[DMODEL * DMODEL];
__device__ __nv_bfloat16 g_woh[DMODEL * DMODEL], g_wol[DMODEL * DMODEL];
__device__ __nv_bfloat16 g_wkh[HDIM * DMODEL],   g_wkl[HDIM * DMODEL];
__device__ __nv_bfloat16 g_wvh[HDIM * DMODEL],   g_wvl[HDIM * DMODEL];
__device__ __nv_bfloat16 g_qbh[MROWS * DMODEL], g_qbl[MROWS * DMODEL];
__device__ __nv_bfloat16 g_kbh[MROWS * HDIM],   g_kbl[MROWS * HDIM];
__device__ __nv_bfloat16 g_vbh[MROWS * HDIM],   g_vbl[MROWS * HDIM];

// ---------------- helpers ----------------
__device__ __forceinline__ uint32_t smem_to_u32(const void* p) {
    uint32_t a;
    asm("{ .reg .u64 t; cvta.to.shared.u64 t, %1; cvt.u32.u64 %0, t; }" : "=r"(a) : "l"(p));
    return a;
}

#define CP_ASYNC16(saddr, gptr) \
    asm volatile("cp.async.cg.shared.global [%0], [%1], 16;" :: "r"(saddr), "l"(gptr))
#define CP_COMMIT() asm volatile("cp.async.commit_group;" ::: "memory")
#define CP_WAIT(n)  asm volatile("cp.async.wait_group %0;" :: "n"(n) : "memory")

__device__ __forceinline__ void ldsm_x4(uint32_t& r0, uint32_t& r1, uint32_t& r2, uint32_t& r3,
                                        uint32_t addr) {
    asm volatile("ldmatrix.sync.aligned.m8n8.x4.shared.b16 {%0,%1,%2,%3}, [%4];"
                 : "=r"(r0), "=r"(r1), "=r"(r2), "=r"(r3) : "r"(addr));
}
__device__ __forceinline__ void ldsm_x4t(uint32_t& r0, uint32_t& r1, uint32_t& r2, uint32_t& r3,
                                         uint32_t addr) {
    asm volatile("ldmatrix.sync.aligned.m8n8.x4.trans.shared.b16 {%0,%1,%2,%3}, [%4];"
                 : "=r"(r0), "=r"(r1), "=r"(r2), "=r"(r3) : "r"(addr));
}
__device__ __forceinline__ void mma16816(float* d, const uint32_t* a, uint32_t b0, uint32_t b1) {
    asm volatile(
        "mma.sync.aligned.m16n8k16.row.col.f32.bf16.bf16.f32 "
        "{%0,%1,%2,%3}, {%4,%5,%6,%7}, {%8,%9}, {%0,%1,%2,%3};"
        : "+f"(d[0]), "+f"(d[1]), "+f"(d[2]), "+f"(d[3])
        : "r"(a[0]), "r"(a[1]), "r"(a[2]), "r"(a[3]), "r"(b0), "r"(b1));
}
__device__ __forceinline__ uint32_t pack_bf16(float lo, float hi) {
    uint32_t r;
    asm("cvt.rn.bf16x2.f32 %0, %1, %2;" : "=r"(r) : "f"(hi), "f"(lo));
    return r;
}
__device__ __forceinline__ void split1(float v, float& h, float& l) {
    __nv_bfloat16 hb = __float2bfloat16(v);
    h = __bfloat162float(hb);
    l = v - h;
}

// ---------------- batched fp32 -> bf16 hi/lo split (x, Wq, Wk, Wv, Wo in one launch) ----------------
#define SPL_N0 (MROWS * DMODEL)                    // x       : 8388608
#define SPL_N1 (SPL_N0 + DMODEL * DMODEL)          // + Wq    : 12582912
#define SPL_N2 (SPL_N1 + HDIM * DMODEL)            // + Wk    : 12845056
#define SPL_N3 (SPL_N2 + HDIM * DMODEL)            // + Wv    : 13107200
#define SPL_N4 (SPL_N3 + DMODEL * DMODEL)          // + Wo    : 17301504

__global__ void split_all(const float* __restrict__ x,  const float* __restrict__ wq,
                          const float* __restrict__ wk, const float* __restrict__ wv,
                          const float* __restrict__ wo,
                          __nv_bfloat16* __restrict__ xh,  __nv_bfloat16* __restrict__ xl,
                          __nv_bfloat16* __restrict__ qh,  __nv_bfloat16* __restrict__ ql,
                          __nv_bfloat16* __restrict__ kh,  __nv_bfloat16* __restrict__ kl,
                          __nv_bfloat16* __restrict__ vh,  __nv_bfloat16* __restrict__ vl,
                          __nv_bfloat16* __restrict__ oh,  __nv_bfloat16* __restrict__ ol) {
    int i = blockIdx.x * blockDim.x + threadIdx.x;
    if (i >= SPL_N4) return;
    const float* s; __nv_bfloat16 *h, *l; int off;
    if      (i < SPL_N0) { s = x;  h = xh; l = xl; off = i; }
    else if (i < SPL_N1) { s = wq; h = qh; l = ql; off = i - SPL_N0; }
    else if (i < SPL_N2) { s = wk; h = kh; l = kl; off = i - SPL_N1; }
    else if (i < SPL_N3) { s = wv; h = vh; l = vl; off = i - SPL_N2; }
    else                 { s = wo; h = oh; l = ol; off = i - SPL_N3; }
    float v = s[off];
    __nv_bfloat16 hb = __float2bfloat16(v);
    h[off] = hb;
    l[off] = __float2bfloat16(v - __bfloat162float(hb));
}

// ---------------- mma.sync bf16x3 GEMM with fused epilogues (validated) ----------------
// MODE 0: fp32 C.  MODE 1: RoPE + hi/lo split.  MODE 2: hi/lo split.
#define TPITCH 40
#define TILE_B (128 * TPITCH * 2)
#define BUF_B  (4 * TILE_B)

// core body shared by gemm_mma<MODE> and gemm_kv (runtime mode; CTA-uniform branch)
__device__ __forceinline__ void gemm_body(const __nv_bfloat16* Ah, const __nv_bfloat16* Al,
                                          const __nv_bfloat16* Bh, const __nv_bfloat16* Bl,
                                          float* C, __nv_bfloat16* Ohi, __nv_bfloat16* Olo,
                                          const float* cosT, const float* sinT,
                                          int N, int K, int mode, int m0, int n0) {
    const uint32_t sbase = smem_to_u32(dyn_smem);
    const int t = threadIdx.x, wid = t >> 5, lane = t & 31;
    const int wm = wid & 1, wn = wid >> 1;

    const __nv_bfloat16* srcs[4] = { Ah + (size_t)m0 * K, Al + (size_t)m0 * K,
                                     Bh + (size_t)n0 * K, Bl + (size_t)n0 * K };
    const int r0c = (t + 0)   >> 2, s0c = (t + 0)   & 3;
    const int r1c = (t + 256) >> 2, s1c = (t + 256) & 3;

    float acc[4][4][4];
    #pragma unroll
    for (int i = 0; i < 4; i++)
        #pragma unroll
        for (int j = 0; j < 4; j++)
            #pragma unroll
            for (int e = 0; e < 4; e++) acc[i][j][e] = 0.f;

    const int NC = K / 32;
    const int a_row = lane & 15, a_c8 = lane >> 4;
    const int b_row = (lane & 7) + ((lane >> 4) << 3), b_c8 = (lane >> 3) & 1;

    auto load_chunk = [&](int c, int buf) {
        const int k0 = c * 32;
        uint32_t sb = sbase + buf * BUF_B;
        #pragma unroll
        for (int tile = 0; tile < 4; tile++) {
            const __nv_bfloat16* s = srcs[tile] + k0;
            uint32_t td = sb + tile * TILE_B;
            CP_ASYNC16(td + (uint32_t)(r0c * TPITCH + s0c * 8) * 2, s + (size_t)r0c * K + s0c * 8);
            CP_ASYNC16(td + (uint32_t)(r1c * TPITCH + s1c * 8) * 2, s + (size_t)r1c * K + s1c * 8);
        }
    };

    load_chunk(0, 0);
    CP_COMMIT();

    for (int c = 0; c < NC; c++) {
        if (c + 1 < NC) { load_chunk(c + 1, (c + 1) & 1); CP_COMMIT(); CP_WAIT(1); }
        else            { CP_WAIT(0); }
        __syncthreads();

        const uint32_t sb  = sbase + (c & 1) * BUF_B;
        const uint32_t sAh = sb, sAl = sb + TILE_B, sBh = sb + 2 * TILE_B, sBl = sb + 3 * TILE_B;

        #pragma unroll
        for (int s = 0; s < 2; s++) {
            const int kc = s * 16;
            uint32_t ah[4][4], al[4][4], bh[4][2], bl[4][2];
            #pragma unroll
            for (int mi = 0; mi < 4; mi++) {
                uint32_t off = (uint32_t)((wm * 64 + mi * 16 + a_row) * TPITCH + kc + a_c8 * 8) * 2;
                ldsm_x4(ah[mi][0], ah[mi][1], ah[mi][2], ah[mi][3], sAh + off);
                ldsm_x4(al[mi][0], al[mi][1], al[mi][2], al[mi][3], sAl + off);
            }
            #pragma unroll
            for (int np = 0; np < 2; np++) {
                uint32_t off = (uint32_t)((wn * 32 + np * 16 + b_row) * TPITCH + kc + b_c8 * 8) * 2;
                uint32_t h0, h1, h2, h3, l0, l1, l2, l3;
                ldsm_x4(h0, h1, h2, h3, sBh + off);
                ldsm_x4(l0, l1, l2, l3, sBl + off);
                bh[np*2][0] = h0; bh[np*2][1] = h1; bh[np*2+1][0] = h2; bh[np*2+1][1] = h3;
                bl[np*2][0] = l0; bl[np*2][1] = l1; bl[np*2+1][0] = l2; bl[np*2+1][1] = l3;
            }
            #pragma unroll
            for (int mi = 0; mi < 4; mi++)
                #pragma unroll
                for (int nj = 0; nj < 4; nj++) {
                    mma16816(acc[mi][nj], ah[mi], bh[nj][0], bh[nj][1]);
                    mma16816(acc[mi][nj], ah[mi], bl[nj][0], bl[nj][1]);
                    mma16816(acc[mi][nj], al[mi], bh[nj][0], bh[nj][1]);
                }
        }
        __syncthreads();
    }

    const int dr = lane >> 2, dc = (lane & 3) * 2;
    #pragma unroll
    for (int mi = 0; mi < 4; mi++) {
        const int rowb = m0 + wm * 64 + mi * 16 + dr;
        #pragma unroll
        for (int nj = 0; nj < 4; nj++) {
            const int col = n0 + wn * 32 + nj * 8 + dc;
            #pragma unroll
            for (int rr = 0; rr < 2; rr++) {
                const int r = rowb + rr * 8;
                float e0 = acc[mi][nj][rr * 2], e1 = acc[mi][nj][rr * 2 + 1];
                if (mode == 0) {
                    *(float2*)(C + (size_t)r * N + col) = make_float2(e0, e1);
                } else {
                    if (mode == 1) {
                        int s  = r & (SEQ - 1);
                        int p  = (col & (HDIM - 1)) >> 1;
                        float cc = cosT[s * 64 + p], sn = sinT[s * 64 + p];
                        float o0 = e0 * cc - e1 * sn;
                        float o1 = e0 * sn + e1 * cc;
                        e0 = o0; e1 = o1;
                    }
                    float h0, l0f, h1, l1f;
                    split1(e0, h0, l0f); split1(e1, h1, l1f);
                    *(__nv_bfloat162*)(Ohi + (size_t)r * N + col) =
                        __nv_bfloat162(__float2bfloat16(h0),  __float2bfloat16(h1));
                    *(__nv_bfloat162*)(Olo + (size_t)r * N + col) =
                        __nv_bfloat162(__float2bfloat16(l0f), __float2bfloat16(l1f));
                }
            }
        }
    }
}

template <int MODE>
__global__ __launch_bounds__(256) void gemm_mma(const __nv_bfloat16* __restrict__ Ah,
                                                const __nv_bfloat16* __restrict__ Al,
                                                const __nv_bfloat16* __restrict__ Bh,
                                                const __nv_bfloat16* __restrict__ Bl,
                                                float* __restrict__ C,
                                                __nv_bfloat16* __restrict__ Ohi,
                                                __nv_bfloat16* __restrict__ Olo,
                                                const float* __restrict__ cosT,
                                                const float* __restrict__ sinT,
                                                int N, int K) {
    gemm_body(Ah, Al, Bh, Bl, C, Ohi, Olo, cosT, sinT, N, K, MODE,
              blockIdx.y * 128, blockIdx.x * 128);
}

// merged K-proj (z=0, RoPE+split) and V-proj (z=1, split) in ONE launch, grid (1, M/128, 2)
__global__ __launch_bounds__(256) void gemm_kv(const __nv_bfloat16* __restrict__ Ah,
                                               const __nv_bfloat16* __restrict__ Al,
                                               const __nv_bfloat16* __restrict__ Kwh,
                                               const __nv_bfloat16* __restrict__ Kwl,
                                               const __nv_bfloat16* __restrict__ Vwh,
                                               const __nv_bfloat16* __restrict__ Vwl,
                                               __nv_bfloat16* __restrict__ Khi,
                                               __nv_bfloat16* __restrict__ Klo,
                                               __nv_bfloat16* __restrict__ Vhi,
                                               __nv_bfloat16* __restrict__ Vlo,
                                               const float* __restrict__ cosT,
                                               const float* __restrict__ sinT,
                                               int K) {
    if (blockIdx.z == 0)
        gemm_body(Ah, Al, Kwh, Kwl, nullptr, Khi, Klo, cosT, sinT, HDIM, K, 1,
                  blockIdx.y * 128, 0);
    else
        gemm_body(Ah, Al, Vwh, Vwl, nullptr, Vhi, Vlo, nullptr, nullptr, HDIM, K, 2,
                  blockIdx.y * 128, 0);
}

// ---------------- tensor-core flash attention (VALIDATED R9: heads folded, KV64 double-buffered) ----------------
#define QP    136
#define QPB   (QP * 2)               // 272 bytes/row
#define ATT_SQH 0
#define ATT_SQL (128 * QPB)          // 34816
#define ATT_KV0 (2 * 128 * QPB)      // 69632
#define KVT   (64 * QPB)             // 17408
#define KVBUF (4 * KVT)              // 69632 : Kh, Kl, Vh, Vl
#define ATT_SMEM (ATT_KV0 + 2 * KVBUF)   // 208896

__global__ __launch_bounds__(256, 1) void attn_mma(
    const __nv_bfloat16* __restrict__ Qh, const __nv_bfloat16* __restrict__ Ql,
    const __nv_bfloat16* __restrict__ Kh, const __nv_bfloat16* __restrict__ Kl,
    const __nv_bfloat16* __restrict__ Vh, const __nv_bfloat16* __restrict__ Vl,
    __nv_bfloat16* __restrict__ Ahi, __nv_bfloat16* __restrict__ Alo) {
    const uint32_t sb = smem_to_u32(dyn_smem);
    const int t = threadIdx.x, w = t >> 5, lane = t & 31;
    const int b = blockIdx.z, hg = blockIdx.y;       // head group (8 heads)
    const int qt = gridDim.x - 1 - blockIdx.x;       // big tiles first
    const int q0 = qt * 16;                          // 16 q-rows per CTA
    const int nt = qt / 4 + 1;                       // causal KV tiles of 64
    const float scale = 0.08838834764831845f;

    const int a_row = lane & 15, a_c8 = lane >> 4;
    const int kb_row = (lane & 7) + ((lane >> 4) << 3);
    const int kb_c8 = (lane >> 3) & 1;
    const int v_row = (lane & 7) + (((lane >> 3) & 1) << 3);
    const int v_c8 = lane >> 4;
    const int dr = lane >> 2, dc = (lane & 3) * 2;

    // ---- load Q: smem row m (0..127) = head hg*8 + m/16, q-row q0 + (m&15) ----
    {
        const __nv_bfloat16* qsrc[2] = { Qh, Ql };
        #pragma unroll
        for (int half = 0; half < 2; half++) {
            uint32_t dst = sb + (half ? ATT_SQL : ATT_SQH);
            #pragma unroll
            for (int it = 0; it < 8; it++) {
                int idx = t + it * 256;              // 0..2047 = 128 rows x 16 chunks
                int m = idx >> 4, c = idx & 15;
                int head = hg * 8 + (m >> 4);
                const __nv_bfloat16* s = qsrc[half]
                    + ((size_t)(b * SEQ + q0 + (m & 15))) * DMODEL + head * HDIM + c * 8;
                CP_ASYNC16(dst + (uint32_t)(m * QPB + c * 16), s);
            }
        }
    }
    auto load_kv = [&](int tile, int buf) {
        const size_t base = (size_t)(b * SEQ + tile * 64) * HDIM;
        const __nv_bfloat16* srcs[4] = { Kh + base, Kl + base, Vh + base, Vl + base };
        uint32_t bb = sb + ATT_KV0 + buf * KVBUF;
        #pragma unroll
        for (int part = 0; part < 4; part++) {
            #pragma unroll
            for (int it = 0; it < 4; it++) {
                int idx = t + it * 256;              // 0..1023 = 64 rows x 16 chunks
                int row = idx >> 4, c = idx & 15;
                CP_ASYNC16(bb + (uint32_t)(part * KVT + row * QPB + c * 16),
                           srcs[part] + (size_t)row * HDIM + c * 8);
            }
        }
    };
    load_kv(0, 0);
    CP_COMMIT();

    float o[16][4];
    #pragma unroll
    for (int nj = 0; nj < 16; nj++)
        #pragma unroll
        for (int e = 0; e < 4; e++) o[nj][e] = 0.f;
    float m0 = -1e30f, m1 = -1e30f, l0 = 0.f, l1 = 0.f;
    const int row0 = q0 + dr, row1 = row0 + 8;       // same q-rows for every warp

    const uint32_t bQh = sb + ATT_SQH, bQl = sb + ATT_SQL;

    for (int tt = 0; tt < nt; tt++) {
        if (tt + 1 < nt) { load_kv(tt + 1, (tt + 1) & 1); CP_COMMIT(); CP_WAIT(1); }
        else             { CP_WAIT(0); }
        __syncthreads();

        const int kv0 = tt * 64;
        const uint32_t bKh = sb + ATT_KV0 + (tt & 1) * KVBUF;
        const uint32_t bKl = bKh + KVT, bVh = bKh + 2 * KVT, bVl = bKh + 3 * KVT;

        // ---- S = Q K^T (bf16x3) ----
        float s[8][4];
        #pragma unroll
        for (int nj = 0; nj < 8; nj++)
            #pragma unroll
            for (int e = 0; e < 4; e++) s[nj][e] = 0.f;

        #pragma unroll
        for (int k = 0; k < 8; k++) {
            uint32_t qoff = (uint32_t)((w * 16 + a_row) * QPB + (k * 16 + a_c8 * 8) * 2);
            uint32_t ah[4], al[4];
            ldsm_x4(ah[0], ah[1], ah[2], ah[3], bQh + qoff);
            ldsm_x4(al[0], al[1], al[2], al[3], bQl + qoff);
            #pragma unroll
            for (int np = 0; np < 4; np++) {
                uint32_t koff = (uint32_t)((np * 16 + kb_row) * QPB + (k * 16 + kb_c8 * 8) * 2);
                uint32_t h0, h1, h2, h3, lo0, lo1, lo2, lo3;
                ldsm_x4(h0, h1, h2, h3, bKh + koff);
                ldsm_x4(lo0, lo1, lo2, lo3, bKl + koff);
                mma16816(s[2*np],     ah, h0, h1);
                mma16816(s[2*np],     ah, lo0, lo1);
                mma16816(s[2*np],     al, h0, h1);
                mma16816(s[2*np + 1], ah, h2, h3);
                mma16816(s[2*np + 1], ah, lo2, lo3);
                mma16816(s[2*np + 1], al, h2, h3);
            }
        }

        // ---- scale + causal mask (row0/row1 identical across warps) ----
        const bool domask = (kv0 + 63 > q0);
        #pragma unroll
        for (int nj = 0; nj < 8; nj++) {
            #pragma unroll
            for (int e = 0; e < 4; e++) s[nj][e] *= scale;
            if (domask) {
                int cg = kv0 + nj * 8 + dc;
                if (cg     > row0) s[nj][0] = -1e30f;
                if (cg + 1 > row0) s[nj][1] = -1e30f;
                if (cg     > row1) s[nj][2] = -1e30f;
                if (cg + 1 > row1) s[nj][3] = -1e30f;
            }
        }

        // ---- online softmax ----
        float mx0 = -1e30f, mx1 = -1e30f;
        #pragma unroll
        for (int nj = 0; nj < 8; nj++) {
            mx0 = fmaxf(mx0, fmaxf(s[nj][0], s[nj][1]));
            mx1 = fmaxf(mx1, fmaxf(s[nj][2], s[nj][3]));
        }
        mx0 = fmaxf(mx0, __shfl_xor_sync(0xffffffffu, mx0, 1));
        mx0 = fmaxf(mx0, __shfl_xor_sync(0xffffffffu, mx0, 2));
        mx1 = fmaxf(mx1, __shfl_xor_sync(0xffffffffu, mx1, 1));
        mx1 = fmaxf(mx1, __shfl_xor_sync(0xffffffffu, mx1, 2));
        float mn0 = fmaxf(m0, mx0), mn1 = fmaxf(m1, mx1);
        float c0 = __expf(m0 - mn0), c1 = __expf(m1 - mn1);
        float sum0 = 0.f, sum1 = 0.f;
        #pragma unroll
        for (int nj = 0; nj < 8; nj++) {
            s[nj][0] = __expf(s[nj][0] - mn0); sum0 += s[nj][0];
            s[nj][1] = __expf(s[nj][1] - mn0); sum0 += s[nj][1];
            s[nj][2] = __expf(s[nj][2] - mn1); sum1 += s[nj][2];
            s[nj][3] = __expf(s[nj][3] - mn1); sum1 += s[nj][3];
        }
        sum0 += __shfl_xor_sync(0xffffffffu, sum0, 1);
        sum0 += __shfl_xor_sync(0xffffffffu, sum0, 2);
        sum1 += __shfl_xor_sync(0xffffffffu, sum1, 1);
        sum1 += __shfl_xor_sync(0xffffffffu, sum1, 2);
        l0 = l0 * c0 + sum0; l1 = l1 * c1 + sum1;
        m0 = mn0; m1 = mn1;
        #pragma unroll
        for (int nj = 0; nj < 16; nj++) {
            o[nj][0] *= c0; o[nj][1] *= c0;
            o[nj][2] *= c1; o[nj][3] *= c1;
        }

        // ---- O += P V (bf16x3; P split in registers) ----
        #pragma unroll
        for (int kq = 0; kq < 4; kq++) {
            float ph[8], pl[8];
            #pragma unroll
            for (int e = 0; e < 4; e++) {
                float p0 = s[2*kq][e], p1 = s[2*kq + 1][e];
                split1(p0, ph[e], pl[e]);
                split1(p1, ph[4 + e], pl[4 + e]);
            }
            uint32_t pah[4], pal[4];
            pah[0] = pack_bf16(ph[0], ph[1]); pah[1] = pack_bf16(ph[2], ph[3]);
            pah[2] = pack_bf16(ph[4], ph[5]); pah[3] = pack_bf16(ph[6], ph[7]);
            pal[0] = pack_bf16(pl[0], pl[1]); pal[1] = pack_bf16(pl[2], pl[3]);
            pal[2] = pack_bf16(pl[4], pl[5]); pal[3] = pack_bf16(pl[6], pl[7]);

            #pragma unroll
            for (int np = 0; np < 8; np++) {
                uint32_t voff = (uint32_t)((kq * 16 + v_row) * QPB + (np * 16 + v_c8 * 8) * 2);
                uint32_t h0, h1, h2, h3, lo0, lo1, lo2, lo3;
                ldsm_x4t(h0, h1, h2, h3, bVh + voff);
                ldsm_x4t(lo0, lo1, lo2, lo3, bVl + voff);
                mma16816(o[2*np],     pah, h0, h1);
                mma16816(o[2*np],     pah, lo0, lo1);
                mma16816(o[2*np],     pal, h0, h1);
                mma16816(o[2*np + 1], pah, h2, h3);
                mma16816(o[2*np + 1], pah, lo2, lo3);
                mma16816(o[2*np + 1], pal, h2, h3);
            }
        }
        __syncthreads();
    }

    // ---- epilogue: normalize + hi/lo split, warp w's head = hg*8+w ----
    const float inv0 = 1.f / l0, inv1 = 1.f / l1;
    const int head = hg * 8 + w;
    const size_t ob0 = (size_t)(b * SEQ + row0) * DMODEL + head * HDIM;
    const size_t ob1 = (size_t)(b * SEQ + row1) * DMODEL + head * HDIM;
    #pragma unroll
    for (int nj = 0; nj < 16; nj++) {
        float v00 = o[nj][0] * inv0, v01 = o[nj][1] * inv0;
        float v10 = o[nj][2] * inv1, v11 = o[nj][3] * inv1;
        float h0, l0f, h1, l1f;
        split1(v00, h0, l0f); split1(v01, h1, l1f);
        *(__nv_bfloat162*)(Ahi + ob0 + nj * 8 + dc) =
            __nv_bfloat162(__float2bfloat16(h0),  __float2bfloat16(h1));
        *(__nv_bfloat162*)(Alo + ob0 + nj * 8 + dc) =
            __nv_bfloat162(__float2bfloat16(l0f), __float2bfloat16(l1f));
        split1(v10, h0, l0f); split1(v11, h1, l1f);
        *(__nv_bfloat162*)(Ahi + ob1 + nj * 8 + dc) =
            __nv_bfloat162(__float2bfloat16(h0),  __float2bfloat16(h1));
        *(__nv_bfloat162*)(Alo + ob1 + nj * 8 + dc) =
            __nv_bfloat162(__float2bfloat16(l0f), __float2bfloat16(l1f));
    }
}

// ---------------- launch ----------------
extern "C" void kernel_launch(void* const* d_in, const int* in_sizes, int n_in,
                              void* d_out, int out_size) {
    const float* x  = (const float*)d_in[0];
    const float* Wq = (const float*)d_in[1];
    const float* Wk = (const float*)d_in[2];
    const float* Wv = (const float*)d_in[3];
    const float* Wo = (const float*)d_in[4];
    const float* rc = (const float*)d_in[5];
    const float* rs = (const float*)d_in[6];
    float* out = (float*)d_out;

    __nv_bfloat16 *xh, *xl, *ah, *al, *wqh, *wql, *woh, *wol, *wkh, *wkl, *wvh, *wvl;
    __nv_bfloat16 *qbh, *qbl, *kbh, *kbl, *vbh, *vbl;
    cudaGetSymbolAddress((void**)&xh,  g_xh);  cudaGetSymbolAddress((void**)&xl,  g_xl);
    cudaGetSymbolAddress((void**)&ah,  g_ah);  cudaGetSymbolAddress((void**)&al,  g_al);
    cudaGetSymbolAddress((void**)&wqh, g_wqh); cudaGetSymbolAddress((void**)&wql, g_wql);
    cudaGetSymbolAddress((void**)&woh, g_woh); cudaGetSymbolAddress((void**)&wol, g_wol);
    cudaGetSymbolAddress((void**)&wkh, g_wkh); cudaGetSymbolAddress((void**)&wkl, g_wkl);
    cudaGetSymbolAddress((void**)&wvh, g_wvh); cudaGetSymbolAddress((void**)&wvl, g_wvl);
    cudaGetSymbolAddress((void**)&qbh, g_qbh); cudaGetSymbolAddress((void**)&qbl, g_qbl);
    cudaGetSymbolAddress((void**)&kbh, g_kbh); cudaGetSymbolAddress((void**)&kbl, g_kbl);
    cudaGetSymbolAddress((void**)&vbh, g_vbh); cudaGetSymbolAddress((void**)&vbl, g_vbl);

    const int M = MROWS;
    const int gemmSmem = 2 * BUF_B;
    cudaFuncSetAttribute(gemm_mma<0>, cudaFuncAttributeMaxDynamicSharedMemorySize, gemmSmem);
    cudaFuncSetAttribute(gemm_mma<1>, cudaFuncAttributeMaxDynamicSharedMemorySize, gemmSmem);
    cudaFuncSetAttribute(gemm_kv,     cudaFuncAttributeMaxDynamicSharedMemorySize, gemmSmem);
    cudaFuncSetAttribute(attn_mma,    cudaFuncAttributeMaxDynamicSharedMemorySize, ATT_SMEM);

    // single batched split: x, Wq, Wk, Wv, Wo -> bf16 hi/lo
    split_all<<<(SPL_N4 + 255) / 256, 256>>>(x, Wq, Wk, Wv, Wo,
                                             xh, xl, wqh, wql, wkh, wkl, wvh, wvl, woh, wol);

    // Q projection (RoPE+split epilogue)
    gemm_mma<1><<<dim3(DMODEL / 128, M / 128), 256, gemmSmem>>>(
        xh, xl, wqh, wql, nullptr, qbh, qbl, rc, rs, DMODEL, DMODEL);

    // merged K+V projections (one launch, 64 CTAs)
    gemm_kv<<<dim3(1, M / 128, 2), 256, gemmSmem>>>(
        xh, xl, wkh, wkl, wvh, wvl, kbh, kbl, vbh, vbl, rc, rs, DMODEL);

    // flash attention: heads folded into M, KV64 double-buffered (validated R9)
    attn_mma<<<dim3(SEQ / 16, NHEAD / 8, BATCH), 256, ATT_SMEM>>>(
        qbh, qbl, kbh, kbl, vbh, vbl, ah, al);

    // output projection -> fp32 out
    gemm_mma<0><<<dim3(DMODEL / 128, M / 128), 256, gemmSmem>>>(
        ah, al, woh, wol, out, nullptr, nullptr, nullptr, nullptr, DMODEL, DMODEL);
}

// round 14
// speedup vs baseline: 4.2203x; 1.1328x over previous
#include <cuda_runtime.h>
#include <cuda_bf16.h>
#include <cstdint>

#define SEQ    2048
#define DMODEL 2048
#define NHEAD  16
#define HDIM   128
#define BATCH  2
#define MROWS  (BATCH * SEQ)   // 4096

extern __shared__ char dyn_smem[];

// ---------------- scratch (no allocations allowed) ----------------
__device__ __nv_bfloat16 g_xh[MROWS * DMODEL],  g_xl[MROWS * DMODEL];
__device__ __nv_bfloat16 g_ah[MROWS * DMODEL],  g_al[MROWS * DMODEL];
__device__ __nv_bfloat16 g_wqh[DMODEL * DMODEL], g_wql[DMODEL * DMODEL];
__device__ __nv_bfloat16 g_woh[DMODEL * DMODEL], g_wol[DMODEL * DMODEL];
__device__ __nv_bfloat16 g_wkh[HDIM * DMODEL],   g_wkl[HDIM * DMODEL];
__device__ __nv_bfloat16 g_wvh[HDIM * DMODEL],   g_wvl[HDIM * DMODEL];
__device__ __nv_bfloat16 g_qbh[MROWS * DMODEL], g_qbl[MROWS * DMODEL];
__device__ __nv_bfloat16 g_kbh[MROWS * HDIM],   g_kbl[MROWS * HDIM];
__device__ __nv_bfloat16 g_vbh[MROWS * HDIM],   g_vbl[MROWS * HDIM];

// ---------------- helpers ----------------
__device__ __forceinline__ uint32_t smem_to_u32(const void* p) {
    uint32_t a;
    asm("{ .reg .u64 t; cvta.to.shared.u64 t, %1; cvt.u32.u64 %0, t; }" : "=r"(a) : "l"(p));
    return a;
}

#define CP_ASYNC16(saddr, gptr) \
    asm volatile("cp.async.cg.shared.global [%0], [%1], 16;" :: "r"(saddr), "l"(gptr))
#define CP_COMMIT() asm volatile("cp.async.commit_group;" ::: "memory")
#define CP_WAIT(n)  asm volatile("cp.async.wait_group %0;" :: "n"(n) : "memory")

__device__ __forceinline__ void ldsm_x4(uint32_t& r0, uint32_t& r1, uint32_t& r2, uint32_t& r3,
                                        uint32_t addr) {
    asm volatile("ldmatrix.sync.aligned.m8n8.x4.shared.b16 {%0,%1,%2,%3}, [%4];"
                 : "=r"(r0), "=r"(r1), "=r"(r2), "=r"(r3) : "r"(addr));
}
__device__ __forceinline__ void ldsm_x4t(uint32_t& r0, uint32_t& r1, uint32_t& r2, uint32_t& r3,
                                         uint32_t addr) {
    asm volatile("ldmatrix.sync.aligned.m8n8.x4.trans.shared.b16 {%0,%1,%2,%3}, [%4];"
                 : "=r"(r0), "=r"(r1), "=r"(r2), "=r"(r3) : "r"(addr));
}
__device__ __forceinline__ void mma16816(float* d, const uint32_t* a, uint32_t b0, uint32_t b1) {
    asm volatile(
        "mma.sync.aligned.m16n8k16.row.col.f32.bf16.bf16.f32 "
        "{%0,%1,%2,%3}, {%4,%5,%6,%7}, {%8,%9}, {%0,%1,%2,%3};"
        : "+f"(d[0]), "+f"(d[1]), "+f"(d[2]), "+f"(d[3])
        : "r"(a[0]), "r"(a[1]), "r"(a[2]), "r"(a[3]), "r"(b0), "r"(b1));
}
__device__ __forceinline__ uint32_t pack_bf16(float lo, float hi) {
    uint32_t r;
    asm("cvt.rn.bf16x2.f32 %0, %1, %2;" : "=r"(r) : "f"(hi), "f"(lo));
    return r;
}
__device__ __forceinline__ void split1(float v, float& h, float& l) {
    __nv_bfloat16 hb = __float2bfloat16(v);
    h = __bfloat162float(hb);
    l = v - h;
}

// ---------------- batched fp32 -> bf16 hi/lo split ----------------
#define SPL_N0 (MROWS * DMODEL)
#define SPL_N1 (SPL_N0 + DMODEL * DMODEL)
#define SPL_N2 (SPL_N1 + HDIM * DMODEL)
#define SPL_N3 (SPL_N2 + HDIM * DMODEL)
#define SPL_N4 (SPL_N3 + DMODEL * DMODEL)

__global__ void split_all(const float* __restrict__ x,  const float* __restrict__ wq,
                          const float* __restrict__ wk, const float* __restrict__ wv,
                          const float* __restrict__ wo,
                          __nv_bfloat16* __restrict__ xh,  __nv_bfloat16* __restrict__ xl,
                          __nv_bfloat16* __restrict__ qh,  __nv_bfloat16* __restrict__ ql,
                          __nv_bfloat16* __restrict__ kh,  __nv_bfloat16* __restrict__ kl,
                          __nv_bfloat16* __restrict__ vh,  __nv_bfloat16* __restrict__ vl,
                          __nv_bfloat16* __restrict__ oh,  __nv_bfloat16* __restrict__ ol) {
    int i = blockIdx.x * blockDim.x + threadIdx.x;
    if (i >= SPL_N4) return;
    const float* s; __nv_bfloat16 *h, *l; int off;
    if      (i < SPL_N0) { s = x;  h = xh; l = xl; off = i; }
    else if (i < SPL_N1) { s = wq; h = qh; l = ql; off = i - SPL_N0; }
    else if (i < SPL_N2) { s = wk; h = kh; l = kl; off = i - SPL_N1; }
    else if (i < SPL_N3) { s = wv; h = vh; l = vl; off = i - SPL_N2; }
    else                 { s = wo; h = oh; l = ol; off = i - SPL_N3; }
    float v = s[off];
    __nv_bfloat16 hb = __float2bfloat16(v);
    h[off] = hb;
    l[off] = __float2bfloat16(v - __bfloat162float(hb));
}

// ---------------- mma.sync bf16x3 GEMM body (reg-dieted for 2 CTAs/SM) ----------------
// mode 0: fp32 C.  mode 1: RoPE + hi/lo split.  mode 2: hi/lo split.
// A-frags loaded per-mi (8 regs live) instead of all-at-once (32) -> target <=128 regs.
// MMA issue order per accumulator unchanged -> bit-identical results.
#define TPITCH 40
#define TILE_B (128 * TPITCH * 2)
#define BUF_B  (4 * TILE_B)

__device__ __forceinline__ void gemm_body(const __nv_bfloat16* Ah, const __nv_bfloat16* Al,
                                          const __nv_bfloat16* Bh, const __nv_bfloat16* Bl,
                                          float* C, __nv_bfloat16* Ohi, __nv_bfloat16* Olo,
                                          const float* cosT, const float* sinT,
                                          int N, int K, int mode, int m0, int n0) {
    const uint32_t sbase = smem_to_u32(dyn_smem);
    const int t = threadIdx.x, wid = t >> 5, lane = t & 31;
    const int wm = wid & 1, wn = wid >> 1;

    const __nv_bfloat16* srcs[4] = { Ah + (size_t)m0 * K, Al + (size_t)m0 * K,
                                     Bh + (size_t)n0 * K, Bl + (size_t)n0 * K };
    const int r0c = (t + 0)   >> 2, s0c = (t + 0)   & 3;
    const int r1c = (t + 256) >> 2, s1c = (t + 256) & 3;

    float acc[4][4][4];
    #pragma unroll
    for (int i = 0; i < 4; i++)
        #pragma unroll
        for (int j = 0; j < 4; j++)
            #pragma unroll
            for (int e = 0; e < 4; e++) acc[i][j][e] = 0.f;

    const int NC = K / 32;
    const int a_row = lane & 15, a_c8 = lane >> 4;
    const int b_row = (lane & 7) + ((lane >> 4) << 3), b_c8 = (lane >> 3) & 1;

    auto load_chunk = [&](int c, int buf) {
        const int k0 = c * 32;
        uint32_t sb = sbase + buf * BUF_B;
        #pragma unroll
        for (int tile = 0; tile < 4; tile++) {
            const __nv_bfloat16* s = srcs[tile] + k0;
            uint32_t td = sb + tile * TILE_B;
            CP_ASYNC16(td + (uint32_t)(r0c * TPITCH + s0c * 8) * 2, s + (size_t)r0c * K + s0c * 8);
            CP_ASYNC16(td + (uint32_t)(r1c * TPITCH + s1c * 8) * 2, s + (size_t)r1c * K + s1c * 8);
        }
    };

    load_chunk(0, 0);
    CP_COMMIT();

    for (int c = 0; c < NC; c++) {
        if (c + 1 < NC) { load_chunk(c + 1, (c + 1) & 1); CP_COMMIT(); CP_WAIT(1); }
        else            { CP_WAIT(0); }
        __syncthreads();

        const uint32_t sb  = sbase + (c & 1) * BUF_B;
        const uint32_t sAh = sb, sAl = sb + TILE_B, sBh = sb + 2 * TILE_B, sBl = sb + 3 * TILE_B;

        #pragma unroll
        for (int s = 0; s < 2; s++) {
            const int kc = s * 16;
            uint32_t bh[4][2], bl[4][2];
            #pragma unroll
            for (int np = 0; np < 2; np++) {
                uint32_t off = (uint32_t)((wn * 32 + np * 16 + b_row) * TPITCH + kc + b_c8 * 8) * 2;
                uint32_t h0, h1, h2, h3, l0, l1, l2, l3;
                ldsm_x4(h0, h1, h2, h3, sBh + off);
                ldsm_x4(l0, l1, l2, l3, sBl + off);
                bh[np*2][0] = h0; bh[np*2][1] = h1; bh[np*2+1][0] = h2; bh[np*2+1][1] = h3;
                bl[np*2][0] = l0; bl[np*2][1] = l1; bl[np*2+1][0] = l2; bl[np*2+1][1] = l3;
            }
            #pragma unroll
            for (int mi = 0; mi < 4; mi++) {
                uint32_t ah[4], al[4];
                uint32_t off = (uint32_t)((wm * 64 + mi * 16 + a_row) * TPITCH + kc + a_c8 * 8) * 2;
                ldsm_x4(ah[0], ah[1], ah[2], ah[3], sAh + off);
                ldsm_x4(al[0], al[1], al[2], al[3], sAl + off);
                #pragma unroll
                for (int nj = 0; nj < 4; nj++) {
                    mma16816(acc[mi][nj], ah, bh[nj][0], bh[nj][1]);
                    mma16816(acc[mi][nj], ah, bl[nj][0], bl[nj][1]);
                    mma16816(acc[mi][nj], al, bh[nj][0], bh[nj][1]);
                }
            }
        }
        __syncthreads();
    }

    const int dr = lane >> 2, dc = (lane & 3) * 2;
    #pragma unroll
    for (int mi = 0; mi < 4; mi++) {
        const int rowb = m0 + wm * 64 + mi * 16 + dr;
        #pragma unroll
        for (int nj = 0; nj < 4; nj++) {
            const int col = n0 + wn * 32 + nj * 8 + dc;
            #pragma unroll
            for (int rr = 0; rr < 2; rr++) {
                const int r = rowb + rr * 8;
                float e0 = acc[mi][nj][rr * 2], e1 = acc[mi][nj][rr * 2 + 1];
                if (mode == 0) {
                    *(float2*)(C + (size_t)r * N + col) = make_float2(e0, e1);
                } else {
                    if (mode == 1) {
                        int s  = r & (SEQ - 1);
                        int p  = (col & (HDIM - 1)) >> 1;
                        float cc = cosT[s * 64 + p], sn = sinT[s * 64 + p];
                        float o0 = e0 * cc - e1 * sn;
                        float o1 = e0 * sn + e1 * cc;
                        e0 = o0; e1 = o1;
                    }
                    float h0, l0f, h1, l1f;
                    split1(e0, h0, l0f); split1(e1, h1, l1f);
                    *(__nv_bfloat162*)(Ohi + (size_t)r * N + col) =
                        __nv_bfloat162(__float2bfloat16(h0),  __float2bfloat16(h1));
                    *(__nv_bfloat162*)(Olo + (size_t)r * N + col) =
                        __nv_bfloat162(__float2bfloat16(l0f), __float2bfloat16(l1f));
                }
            }
        }
    }
}

// merged Q/K/V projections, one launch. grid (1, M/128, 18):
// z in [0,16): Q-proj n-tile z (RoPE+split). z==16: K (RoPE+split). z==17: V (split).
__global__ __launch_bounds__(256, 2) void gemm_qkv(
    const __nv_bfloat16* __restrict__ xh,  const __nv_bfloat16* __restrict__ xl,
    const __nv_bfloat16* __restrict__ wqh, const __nv_bfloat16* __restrict__ wql,
    const __nv_bfloat16* __restrict__ wkh, const __nv_bfloat16* __restrict__ wkl,
    const __nv_bfloat16* __restrict__ wvh, const __nv_bfloat16* __restrict__ wvl,
    __nv_bfloat16* __restrict__ qbh, __nv_bfloat16* __restrict__ qbl,
    __nv_bfloat16* __restrict__ kbh, __nv_bfloat16* __restrict__ kbl,
    __nv_bfloat16* __restrict__ vbh, __nv_bfloat16* __restrict__ vbl,
    const float* __restrict__ rc, const float* __restrict__ rs) {
    const int z = blockIdx.z;
    const __nv_bfloat16 *Bh, *Bl; __nv_bfloat16 *Ohi, *Olo;
    int N, mode, n0;
    if (z < 16)      { Bh = wqh; Bl = wql; Ohi = qbh; Olo = qbl; N = DMODEL; mode = 1; n0 = z * 128; }
    else if (z == 16){ Bh = wkh; Bl = wkl; Ohi = kbh; Olo = kbl; N = HDIM;   mode = 1; n0 = 0; }
    else             { Bh = wvh; Bl = wvl; Ohi = vbh; Olo = vbl; N = HDIM;   mode = 2; n0 = 0; }
    gemm_body(xh, xl, Bh, Bl, nullptr, Ohi, Olo, rc, rs, N, DMODEL, mode,
              blockIdx.y * 128, n0);
}

// output projection -> fp32
__global__ __launch_bounds__(256, 2) void gemm_out(
    const __nv_bfloat16* __restrict__ Ah, const __nv_bfloat16* __restrict__ Al,
    const __nv_bfloat16* __restrict__ Bh, const __nv_bfloat16* __restrict__ Bl,
    float* __restrict__ C) {
    gemm_body(Ah, Al, Bh, Bl, C, nullptr, nullptr, nullptr, nullptr, DMODEL, DMODEL, 0,
              blockIdx.y * 128, blockIdx.x * 128);
}

// ---------------- tensor-core flash attention (VALIDATED R9: unchanged) ----------------
#define QP    136
#define QPB   (QP * 2)               // 272 bytes/row
#define ATT_SQH 0
#define ATT_SQL (128 * QPB)          // 34816
#define ATT_KV0 (2 * 128 * QPB)      // 69632
#define KVT   (64 * QPB)             // 17408
#define KVBUF (4 * KVT)              // 69632 : Kh, Kl, Vh, Vl
#define ATT_SMEM (ATT_KV0 + 2 * KVBUF)   // 208896

__global__ __launch_bounds__(256, 1) void attn_mma(
    const __nv_bfloat16* __restrict__ Qh, const __nv_bfloat16* __restrict__ Ql,
    const __nv_bfloat16* __restrict__ Kh, const __nv_bfloat16* __restrict__ Kl,
    const __nv_bfloat16* __restrict__ Vh, const __nv_bfloat16* __restrict__ Vl,
    __nv_bfloat16* __restrict__ Ahi, __nv_bfloat16* __restrict__ Alo) {
    const uint32_t sb = smem_to_u32(dyn_smem);
    const int t = threadIdx.x, w = t >> 5, lane = t & 31;
    const int b = blockIdx.z, hg = blockIdx.y;
    const int qt = gridDim.x - 1 - blockIdx.x;
    const int q0 = qt * 16;
    const int nt = qt / 4 + 1;
    const float scale = 0.08838834764831845f;

    const int a_row = lane & 15, a_c8 = lane >> 4;
    const int kb_row = (lane & 7) + ((lane >> 4) << 3);
    const int kb_c8 = (lane >> 3) & 1;
    const int v_row = (lane & 7) + (((lane >> 3) & 1) << 3);
    const int v_c8 = lane >> 4;
    const int dr = lane >> 2, dc = (lane & 3) * 2;

    {
        const __nv_bfloat16* qsrc[2] = { Qh, Ql };
        #pragma unroll
        for (int half = 0; half < 2; half++) {
            uint32_t dst = sb + (half ? ATT_SQL : ATT_SQH);
            #pragma unroll
            for (int it = 0; it < 8; it++) {
                int idx = t + it * 256;
                int m = idx >> 4, c = idx & 15;
                int head = hg * 8 + (m >> 4);
                const __nv_bfloat16* s = qsrc[half]
                    + ((size_t)(b * SEQ + q0 + (m & 15))) * DMODEL + head * HDIM + c * 8;
                CP_ASYNC16(dst + (uint32_t)(m * QPB + c * 16), s);
            }
        }
    }
    auto load_kv = [&](int tile, int buf) {
        const size_t base = (size_t)(b * SEQ + tile * 64) * HDIM;
        const __nv_bfloat16* srcs[4] = { Kh + base, Kl + base, Vh + base, Vl + base };
        uint32_t bb = sb + ATT_KV0 + buf * KVBUF;
        #pragma unroll
        for (int part = 0; part < 4; part++) {
            #pragma unroll
            for (int it = 0; it < 4; it++) {
                int idx = t + it * 256;
                int row = idx >> 4, c = idx & 15;
                CP_ASYNC16(bb + (uint32_t)(part * KVT + row * QPB + c * 16),
                           srcs[part] + (size_t)row * HDIM + c * 8);
            }
        }
    };
    load_kv(0, 0);
    CP_COMMIT();

    float o[16][4];
    #pragma unroll
    for (int nj = 0; nj < 16; nj++)
        #pragma unroll
        for (int e = 0; e < 4; e++) o[nj][e] = 0.f;
    float m0 = -1e30f, m1 = -1e30f, l0 = 0.f, l1 = 0.f;
    const int row0 = q0 + dr, row1 = row0 + 8;

    const uint32_t bQh = sb + ATT_SQH, bQl = sb + ATT_SQL;

    for (int tt = 0; tt < nt; tt++) {
        if (tt + 1 < nt) { load_kv(tt + 1, (tt + 1) & 1); CP_COMMIT(); CP_WAIT(1); }
        else             { CP_WAIT(0); }
        __syncthreads();

        const int kv0 = tt * 64;
        const uint32_t bKh = sb + ATT_KV0 + (tt & 1) * KVBUF;
        const uint32_t bKl = bKh + KVT, bVh = bKh + 2 * KVT, bVl = bKh + 3 * KVT;

        float s[8][4];
        #pragma unroll
        for (int nj = 0; nj < 8; nj++)
            #pragma unroll
            for (int e = 0; e < 4; e++) s[nj][e] = 0.f;

        #pragma unroll
        for (int k = 0; k < 8; k++) {
            uint32_t qoff = (uint32_t)((w * 16 + a_row) * QPB + (k * 16 + a_c8 * 8) * 2);
            uint32_t ah[4], al[4];
            ldsm_x4(ah[0], ah[1], ah[2], ah[3], bQh + qoff);
            ldsm_x4(al[0], al[1], al[2], al[3], bQl + qoff);
            #pragma unroll
            for (int np = 0; np < 4; np++) {
                uint32_t koff = (uint32_t)((np * 16 + kb_row) * QPB + (k * 16 + kb_c8 * 8) * 2);
                uint32_t h0, h1, h2, h3, lo0, lo1, lo2, lo3;
                ldsm_x4(h0, h1, h2, h3, bKh + koff);
                ldsm_x4(lo0, lo1, lo2, lo3, bKl + koff);
                mma16816(s[2*np],     ah, h0, h1);
                mma16816(s[2*np],     ah, lo0, lo1);
                mma16816(s[2*np],     al, h0, h1);
                mma16816(s[2*np + 1], ah, h2, h3);
                mma16816(s[2*np + 1], ah, lo2, lo3);
                mma16816(s[2*np + 1], al, h2, h3);
            }
        }

        const bool domask = (kv0 + 63 > q0);
        #pragma unroll
        for (int nj = 0; nj < 8; nj++) {
            #pragma unroll
            for (int e = 0; e < 4; e++) s[nj][e] *= scale;
            if (domask) {
                int cg = kv0 + nj * 8 + dc;
                if (cg     > row0) s[nj][0] = -1e30f;
                if (cg + 1 > row0) s[nj][1] = -1e30f;
                if (cg     > row1) s[nj][2] = -1e30f;
                if (cg + 1 > row1) s[nj][3] = -1e30f;
            }
        }

        float mx0 = -1e30f, mx1 = -1e30f;
        #pragma unroll
        for (int nj = 0; nj < 8; nj++) {
            mx0 = fmaxf(mx0, fmaxf(s[nj][0], s[nj][1]));
            mx1 = fmaxf(mx1, fmaxf(s[nj][2], s[nj][3]));
        }
        mx0 = fmaxf(mx0, __shfl_xor_sync(0xffffffffu, mx0, 1));
        mx0 = fmaxf(mx0, __shfl_xor_sync(0xffffffffu, mx0, 2));
        mx1 = fmaxf(mx1, __shfl_xor_sync(0xffffffffu, mx1, 1));
        mx1 = fmaxf(mx1, __shfl_xor_sync(0xffffffffu, mx1, 2));
        float mn0 = fmaxf(m0, mx0), mn1 = fmaxf(m1, mx1);
        float c0 = __expf(m0 - mn0), c1 = __expf(m1 - mn1);
        float sum0 = 0.f, sum1 = 0.f;
        #pragma unroll
        for (int nj = 0; nj < 8; nj++) {
            s[nj][0] = __expf(s[nj][0] - mn0); sum0 += s[nj][0];
            s[nj][1] = __expf(s[nj][1] - mn0); sum0 += s[nj][1];
            s[nj][2] = __expf(s[nj][2] - mn1); sum1 += s[nj][2];
            s[nj][3] = __expf(s[nj][3] - mn1); sum1 += s[nj][3];
        }
        sum0 += __shfl_xor_sync(0xffffffffu, sum0, 1);
        sum0 += __shfl_xor_sync(0xffffffffu, sum0, 2);
        sum1 += __shfl_xor_sync(0xffffffffu, sum1, 1);
        sum1 += __shfl_xor_sync(0xffffffffu, sum1, 2);
        l0 = l0 * c0 + sum0; l1 = l1 * c1 + sum1;
        m0 = mn0; m1 = mn1;
        #pragma unroll
        for (int nj = 0; nj < 16; nj++) {
            o[nj][0] *= c0; o[nj][1] *= c0;
            o[nj][2] *= c1; o[nj][3] *= c1;
        }

        #pragma unroll
        for (int kq = 0; kq < 4; kq++) {
            float ph[8], pl[8];
            #pragma unroll
            for (int e = 0; e < 4; e++) {
                float p0 = s[2*kq][e], p1 = s[2*kq + 1][e];
                split1(p0, ph[e], pl[e]);
                split1(p1, ph[4 + e], pl[4 + e]);
            }
            uint32_t pah[4], pal[4];
            pah[0] = pack_bf16(ph[0], ph[1]); pah[1] = pack_bf16(ph[2], ph[3]);
            pah[2] = pack_bf16(ph[4], ph[5]); pah[3] = pack_bf16(ph[6], ph[7]);
            pal[0] = pack_bf16(pl[0], pl[1]); pal[1] = pack_bf16(pl[2], pl[3]);
            pal[2] = pack_bf16(pl[4], pl[5]); pal[3] = pack_bf16(pl[6], pl[7]);

            #pragma unroll
            for (int np = 0; np < 8; np++) {
                uint32_t voff = (uint32_t)((kq * 16 + v_row) * QPB + (np * 16 + v_c8 * 8) * 2);
                uint32_t h0, h1, h2, h3, lo0, lo1, lo2, lo3;
                ldsm_x4t(h0, h1, h2, h3, bVh + voff);
                ldsm_x4t(lo0, lo1, lo2, lo3, bVl + voff);
                mma16816(o[2*np],     pah, h0, h1);
                mma16816(o[2*np],     pah, lo0, lo1);
                mma16816(o[2*np],     pal, h0, h1);
                mma16816(o[2*np + 1], pah, h2, h3);
                mma16816(o[2*np + 1], pah, lo2, lo3);
                mma16816(o[2*np + 1], pal, h2, h3);
            }
        }
        __syncthreads();
    }

    const float inv0 = 1.f / l0, inv1 = 1.f / l1;
    const int head = hg * 8 + w;
    const size_t ob0 = (size_t)(b * SEQ + row0) * DMODEL + head * HDIM;
    const size_t ob1 = (size_t)(b * SEQ + row1) * DMODEL + head * HDIM;
    #pragma unroll
    for (int nj = 0; nj < 16; nj++) {
        float v00 = o[nj][0] * inv0, v01 = o[nj][1] * inv0;
        float v10 = o[nj][2] * inv1, v11 = o[nj][3] * inv1;
        float h0, l0f, h1, l1f;
        split1(v00, h0, l0f); split1(v01, h1, l1f);
        *(__nv_bfloat162*)(Ahi + ob0 + nj * 8 + dc) =
            __nv_bfloat162(__float2bfloat16(h0),  __float2bfloat16(h1));
        *(__nv_bfloat162*)(Alo + ob0 + nj * 8 + dc) =
            __nv_bfloat162(__float2bfloat16(l0f), __float2bfloat16(l1f));
        split1(v10, h0, l0f); split1(v11, h1, l1f);
        *(__nv_bfloat162*)(Ahi + ob1 + nj * 8 + dc) =
            __nv_bfloat162(__float2bfloat16(h0),  __float2bfloat16(h1));
        *(__nv_bfloat162*)(Alo + ob1 + nj * 8 + dc) =
            __nv_bfloat162(__float2bfloat16(l0f), __float2bfloat16(l1f));
    }
}

// ---------------- launch ----------------
extern "C" void kernel_launch(void* const* d_in, const int* in_sizes, int n_in,
                              void* d_out, int out_size) {
    const float* x  = (const float*)d_in[0];
    const float* Wq = (const float*)d_in[1];
    const float* Wk = (const float*)d_in[2];
    const float* Wv = (const float*)d_in[3];
    const float* Wo = (const float*)d_in[4];
    const float* rc = (const float*)d_in[5];
    const float* rs = (const float*)d_in[6];
    float* out = (float*)d_out;

    __nv_bfloat16 *xh, *xl, *ah, *al, *wqh, *wql, *woh, *wol, *wkh, *wkl, *wvh, *wvl;
    __nv_bfloat16 *qbh, *qbl, *kbh, *kbl, *vbh, *vbl;
    cudaGetSymbolAddress((void**)&xh,  g_xh);  cudaGetSymbolAddress((void**)&xl,  g_xl);
    cudaGetSymbolAddress((void**)&ah,  g_ah);  cudaGetSymbolAddress((void**)&al,  g_al);
    cudaGetSymbolAddress((void**)&wqh, g_wqh); cudaGetSymbolAddress((void**)&wql, g_wql);
    cudaGetSymbolAddress((void**)&woh, g_woh); cudaGetSymbolAddress((void**)&wol, g_wol);
    cudaGetSymbolAddress((void**)&wkh, g_wkh); cudaGetSymbolAddress((void**)&wkl, g_wkl);
    cudaGetSymbolAddress((void**)&wvh, g_wvh); cudaGetSymbolAddress((void**)&wvl, g_wvl);
    cudaGetSymbolAddress((void**)&qbh, g_qbh); cudaGetSymbolAddress((void**)&qbl, g_qbl);
    cudaGetSymbolAddress((void**)&kbh, g_kbh); cudaGetSymbolAddress((void**)&kbl, g_kbl);
    cudaGetSymbolAddress((void**)&vbh, g_vbh); cudaGetSymbolAddress((void**)&vbl, g_vbl);

    const int M = MROWS;
    const int gemmSmem = 2 * BUF_B;
    cudaFuncSetAttribute(gemm_qkv, cudaFuncAttributeMaxDynamicSharedMemorySize, gemmSmem);
    cudaFuncSetAttribute(gemm_out, cudaFuncAttributeMaxDynamicSharedMemorySize, gemmSmem);
    cudaFuncSetAttribute(attn_mma, cudaFuncAttributeMaxDynamicSharedMemorySize, ATT_SMEM);

    // single batched split
    split_all<<<(SPL_N4 + 255) / 256, 256>>>(x, Wq, Wk, Wv, Wo,
                                             xh, xl, wqh, wql, wkh, wkl, wvh, wvl, woh, wol);

    // merged Q/K/V projections, one launch (576 CTAs)
    gemm_qkv<<<dim3(1, M / 128, 18), 256, gemmSmem>>>(
        xh, xl, wqh, wql, wkh, wkl, wvh, wvl,
        qbh, qbl, kbh, kbl, vbh, vbl, rc, rs);

    // flash attention (validated)
    attn_mma<<<dim3(SEQ / 16, NHEAD / 8, BATCH), 256, ATT_SMEM>>>(
        qbh, qbl, kbh, kbl, vbh, vbl, ah, al);

    // output projection -> fp32 out
    gemm_out<<<dim3(DMODEL / 128, M / 128), 256, gemmSmem>>>(ah, al, woh, wol, out);
}